// round 10
// baseline (speedup 1.0000x reference)
#include <cuda_runtime.h>
#include <cuda_fp16.h>
#include <stdint.h>
#include <math.h>

#define GG 4
#define NN 50000
#define EE 800000
#define BB 32
#define FIN 64
#define HH 128
#define NHEADS 8
#define HD 16
#define GN (GG*NN)
#define GE (GG*EE)
#define GBH (GG*BB*HH)
#define NNODES 50000
#define TILES 49   // ceil(NN/1024)

// ---------------- scratch (device globals; no allocation allowed) -------------
__device__ __half g_xh[(size_t)GN*FIN];     // fp16 copy of x
__device__ __half g_a1h[(size_t)GN*HH];     // relu(layer1) fp16
__device__ __half g_a2h[(size_t)GN*HH];     // relu(layer2) fp16
__device__ __half g_w1h[FIN*HH];
__device__ __half g_w2h[HH*HH];
__device__ int   g_degi[GN];
__device__ float g_dinv[GN];
__device__ int   g_off[GG*(NN+1)];
__device__ int   g_cur[GN];
__device__ int   g_tsum[GG*TILES];
__device__ unsigned g_csr[(size_t)GE];      // packed {norm-fp16:hi16, row-u16:lo16}
__device__ int   g_bstart[GG*(BB+1)];
__device__ float g_emb[GBH];                // pooled means
__device__ float g_pooled[GG*HH];

// ---------------- mma / ldmatrix helpers ------------------------------------------
__device__ __forceinline__ unsigned cvta_sm(const void* p) {
    return (unsigned)__cvta_generic_to_shared(p);
}
__device__ __forceinline__ void ldmx4(unsigned& r0, unsigned& r1, unsigned& r2, unsigned& r3, unsigned a) {
    asm volatile("ldmatrix.sync.aligned.m8n8.x4.shared.b16 {%0,%1,%2,%3},[%4];"
        : "=r"(r0), "=r"(r1), "=r"(r2), "=r"(r3) : "r"(a));
}
__device__ __forceinline__ void ldmx4t(unsigned& r0, unsigned& r1, unsigned& r2, unsigned& r3, unsigned a) {
    asm volatile("ldmatrix.sync.aligned.m8n8.x4.trans.shared.b16 {%0,%1,%2,%3},[%4];"
        : "=r"(r0), "=r"(r1), "=r"(r2), "=r"(r3) : "r"(a));
}
__device__ __forceinline__ void mma16816(float* d, unsigned a0, unsigned a1, unsigned a2, unsigned a3,
                                         unsigned b0, unsigned b1) {
    asm volatile("mma.sync.aligned.m16n8k16.row.col.f32.f16.f16.f32 "
        "{%0,%1,%2,%3},{%4,%5,%6,%7},{%8,%9},{%0,%1,%2,%3};"
        : "+f"(d[0]), "+f"(d[1]), "+f"(d[2]), "+f"(d[3])
        : "r"(a0), "r"(a1), "r"(a2), "r"(a3), "r"(b0), "r"(b1));
}
__device__ __forceinline__ float rec_norm(unsigned r) {
    return __half2float(__ushort_as_half((unsigned short)(r >> 16)));
}

// ---------------- conversions ------------------------------------------------------
__global__ void k_xcvt(const float* __restrict__ x) {
    size_t i = (size_t)blockIdx.x*blockDim.x + threadIdx.x;
    if (i >= (size_t)GN*FIN/8) return;
    const float4* xs = (const float4*)x;
    float4 f0 = xs[2*i], f1 = xs[2*i+1];
    __half2 h0 = __floats2half2_rn(f0.x, f0.y);
    __half2 h1 = __floats2half2_rn(f0.z, f0.w);
    __half2 h2 = __floats2half2_rn(f1.x, f1.y);
    __half2 h3 = __floats2half2_rn(f1.z, f1.w);
    uint4 o = make_uint4(*(unsigned*)&h0, *(unsigned*)&h1, *(unsigned*)&h2, *(unsigned*)&h3);
    ((uint4*)g_xh)[i] = o;
}
// merged: W conversions + pooled zero + bucket bounds
__global__ void k_misc(const float* __restrict__ W1, const float* __restrict__ W2,
                       const int* __restrict__ batch) {
    int i = blockIdx.x*blockDim.x + threadIdx.x;
    if (i < FIN*HH) g_w1h[i] = __float2half_rn(W1[i]);
    if (i < HH*HH)  g_w2h[i] = __float2half_rn(W2[i]);
    if (i < GG*HH)  g_pooled[i] = 0.f;
    if (i < GG*BB) {
        int g = i >> 5, b = i & 31;
        const int* bt = batch + (size_t)g*NN;
        int lo = 0, hi = NN;
        while (lo < hi) {
            int mid = (lo + hi) >> 1;
            if (bt[mid] < b) lo = mid + 1; else hi = mid;
        }
        g_bstart[g*(BB+1) + b] = lo;
        if (b == 0) g_bstart[g*(BB+1) + BB] = NN;
    }
}

// ---------------- CSR build ------------------------------------------------------
__global__ void k_count(const int* __restrict__ ei) {
    int idx = blockIdx.x*blockDim.x + threadIdx.x;
    if (idx >= GE) return;
    int g = idx / EE, e = idx - g*EE;
    int col = ei[(size_t)g*2*EE + EE + e];
    atomicAdd(&g_degi[g*NN + col], 1);
}
__global__ void k_scan1() {
    int g = blockIdx.x / TILES, t = blockIdx.x % TILES;
    int tid = threadIdx.x, lane = tid & 31, wid = tid >> 5;
    __shared__ int wtot[32];
    int i = t*1024 + tid;
    int c = (i < NN) ? g_degi[g*NN + i] : 0;
    int v = c;
#pragma unroll
    for (int o = 1; o < 32; o <<= 1) {
        int u = __shfl_up_sync(~0u, v, o);
        if (lane >= o) v += u;
    }
    if (lane == 31) wtot[wid] = v;
    __syncthreads();
    if (wid == 0) {
        int w2 = wtot[lane];
#pragma unroll
        for (int o = 1; o < 32; o <<= 1) {
            int u = __shfl_up_sync(~0u, w2, o);
            if (lane >= o) w2 += u;
        }
        wtot[lane] = w2;
    }
    __syncthreads();
    int excl = (wid > 0 ? wtot[wid-1] : 0) + v - c;
    if (i < NN) {
        g_off[g*(NN+1) + i] = excl;
        g_dinv[g*NN + i] = rsqrtf((float)(c + 1));
    }
    if (tid == 0) g_tsum[blockIdx.x] = wtot[31];
}
// scan3 merged with scan2: each block computes its own tile base from g_tsum
__global__ void k_scan3m() {
    int g = blockIdx.x / TILES, t = blockIdx.x % TILES;
    int tid = threadIdx.x;
    __shared__ int part[64];
    __shared__ int sbase;
    if (tid < 64) part[tid] = (tid < t) ? g_tsum[g*TILES + tid] : 0;
    __syncthreads();
    if (tid < 32) {
        int v = part[tid] + part[tid + 32];
#pragma unroll
        for (int o = 16; o; o >>= 1) v += __shfl_xor_sync(~0u, v, o);
        if (tid == 0) sbase = v;
    }
    __syncthreads();
    int i = t*1024 + tid;
    if (i < NN) {
        int o = g_off[g*(NN+1) + i] + sbase;
        g_off[g*(NN+1) + i] = o;
        g_cur[g*NN + i] = o;
    }
    if (blockIdx.x == 0 && tid < GG)
        g_off[tid*(NN+1) + NN] = EE;
}
__global__ void k_fill(const int* __restrict__ ei) {
    int idx = blockIdx.x*blockDim.x + threadIdx.x;
    if (idx >= GE) return;
    int g = idx / EE, e = idx - g*EE;
    const int* bp = ei + (size_t)g*2*EE;
    int row = bp[e], col = bp[EE + e];
    float norm = g_dinv[g*NN + row] * g_dinv[g*NN + col];
    unsigned rec = (unsigned)row |
        ((unsigned)__half_as_ushort(__float2half_rn(norm)) << 16);
    int pos = atomicAdd(&g_cur[g*NN + col], 1);
    g_csr[(size_t)g*EE + pos] = rec;
}

// ---------------- fused gather + tensor-core matmul per layer ----------------------
// relu( (D^-1/2 A D^-1/2 + selfloop) src @ W + b ) -> fp16 hout
// 256 threads; block = 128 nodes; warp gathers 16 rows into smem (records loaded
// cooperatively, broadcast via shfl), then block does a 128x128 mma.
template<int K>
__global__ void __launch_bounds__(256) k_fused(const __half* __restrict__ src,
        const __half* __restrict__ Wh, const float* __restrict__ bias,
        __half* __restrict__ hout) {
    constexpr int AS = K + 8;      // padded A row (halfs)
    constexpr int WS = HH + 8;     // 136
    extern __shared__ __half smh[];
    __half* As = smh;              // 128 * AS
    __half* Ws = smh + 128*AS;     // K * WS
    int tid = threadIdx.x, wid = tid >> 5, lane = tid & 31;
    int base = blockIdx.x * 128;

    // load W tile
    for (int idx = tid; idx < K*16; idx += 256) {
        int r = idx >> 4, c8 = (idx & 15) << 3;
        *(uint4*)(Ws + r*WS + c8) = *(const uint4*)(Wh + r*HH + c8);
    }

    // gather phase: warp handles 16 local rows
    for (int t = 0; t < 16; t++) {
        int rl = wid*16 + t;
        int w = base + rl;
        if (w < GN) {
            int g = w / NN, n = w - g*NN;
            const __half* xg = src + (size_t)g*NN*K;
            float di = g_dinv[w], d2 = di*di;
            int s = g_off[g*(NN+1) + n], e2 = g_off[g*(NN+1) + n + 1];
            const unsigned* cs = g_csr + (size_t)g*EE;
            if (K == FIN) {
                float a0, a1;
                {
                    float2 f = __half22float2(*(const __half2*)(xg + (size_t)n*K + lane*2));
                    a0 = f.x*d2; a1 = f.y*d2;
                }
                for (int c = s; c < e2; c += 32) {
                    int m = min(32, e2 - c);
                    unsigned rec = (lane < m) ? __ldg(&cs[c + lane]) : 0u;
                    int j = 0;
                    for (; j + 3 < m; j += 4) {
                        unsigned r0 = __shfl_sync(~0u, rec, j);
                        unsigned r1 = __shfl_sync(~0u, rec, j+1);
                        unsigned r2 = __shfl_sync(~0u, rec, j+2);
                        unsigned r3 = __shfl_sync(~0u, rec, j+3);
                        __half2 h0 = *(const __half2*)(xg + (size_t)(r0 & 0xFFFFu)*K + lane*2);
                        __half2 h1 = *(const __half2*)(xg + (size_t)(r1 & 0xFFFFu)*K + lane*2);
                        __half2 h2 = *(const __half2*)(xg + (size_t)(r2 & 0xFFFFu)*K + lane*2);
                        __half2 h3 = *(const __half2*)(xg + (size_t)(r3 & 0xFFFFu)*K + lane*2);
                        float2 f0 = __half22float2(h0);
                        a0 = fmaf(f0.x, rec_norm(r0), a0);
                        a1 = fmaf(f0.y, rec_norm(r0), a1);
                        float2 f1 = __half22float2(h1);
                        a0 = fmaf(f1.x, rec_norm(r1), a0);
                        a1 = fmaf(f1.y, rec_norm(r1), a1);
                        float2 f2 = __half22float2(h2);
                        a0 = fmaf(f2.x, rec_norm(r2), a0);
                        a1 = fmaf(f2.y, rec_norm(r2), a1);
                        float2 f3 = __half22float2(h3);
                        a0 = fmaf(f3.x, rec_norm(r3), a0);
                        a1 = fmaf(f3.y, rec_norm(r3), a1);
                    }
                    for (; j < m; j++) {
                        unsigned r0 = __shfl_sync(~0u, rec, j);
                        __half2 h0 = *(const __half2*)(xg + (size_t)(r0 & 0xFFFFu)*K + lane*2);
                        float2 f0 = __half22float2(h0);
                        a0 = fmaf(f0.x, rec_norm(r0), a0);
                        a1 = fmaf(f0.y, rec_norm(r0), a1);
                    }
                }
                *(__half2*)(As + rl*AS + lane*2) = __floats2half2_rn(a0, a1);
            } else {
                float a0, a1, a2, a3;
                {
                    uint2 hv = *(const uint2*)(xg + (size_t)n*K + lane*4);
                    float2 f0 = __half22float2(*(__half2*)&hv.x);
                    float2 f1 = __half22float2(*(__half2*)&hv.y);
                    a0 = f0.x*d2; a1 = f0.y*d2; a2 = f1.x*d2; a3 = f1.y*d2;
                }
                for (int c = s; c < e2; c += 32) {
                    int m = min(32, e2 - c);
                    unsigned rec = (lane < m) ? __ldg(&cs[c + lane]) : 0u;
                    int j = 0;
                    for (; j + 3 < m; j += 4) {
                        unsigned r0 = __shfl_sync(~0u, rec, j);
                        unsigned r1 = __shfl_sync(~0u, rec, j+1);
                        unsigned r2 = __shfl_sync(~0u, rec, j+2);
                        unsigned r3 = __shfl_sync(~0u, rec, j+3);
                        uint2 va = *(const uint2*)(xg + (size_t)(r0 & 0xFFFFu)*K + lane*4);
                        uint2 vb = *(const uint2*)(xg + (size_t)(r1 & 0xFFFFu)*K + lane*4);
                        uint2 vc = *(const uint2*)(xg + (size_t)(r2 & 0xFFFFu)*K + lane*4);
                        uint2 vd = *(const uint2*)(xg + (size_t)(r3 & 0xFFFFu)*K + lane*4);
                        {
                            float nrm = rec_norm(r0);
                            float2 f0 = __half22float2(*(__half2*)&va.x);
                            float2 f1 = __half22float2(*(__half2*)&va.y);
                            a0 = fmaf(f0.x, nrm, a0); a1 = fmaf(f0.y, nrm, a1);
                            a2 = fmaf(f1.x, nrm, a2); a3 = fmaf(f1.y, nrm, a3);
                        }
                        {
                            float nrm = rec_norm(r1);
                            float2 f0 = __half22float2(*(__half2*)&vb.x);
                            float2 f1 = __half22float2(*(__half2*)&vb.y);
                            a0 = fmaf(f0.x, nrm, a0); a1 = fmaf(f0.y, nrm, a1);
                            a2 = fmaf(f1.x, nrm, a2); a3 = fmaf(f1.y, nrm, a3);
                        }
                        {
                            float nrm = rec_norm(r2);
                            float2 f0 = __half22float2(*(__half2*)&vc.x);
                            float2 f1 = __half22float2(*(__half2*)&vc.y);
                            a0 = fmaf(f0.x, nrm, a0); a1 = fmaf(f0.y, nrm, a1);
                            a2 = fmaf(f1.x, nrm, a2); a3 = fmaf(f1.y, nrm, a3);
                        }
                        {
                            float nrm = rec_norm(r3);
                            float2 f0 = __half22float2(*(__half2*)&vd.x);
                            float2 f1 = __half22float2(*(__half2*)&vd.y);
                            a0 = fmaf(f0.x, nrm, a0); a1 = fmaf(f0.y, nrm, a1);
                            a2 = fmaf(f1.x, nrm, a2); a3 = fmaf(f1.y, nrm, a3);
                        }
                    }
                    for (; j < m; j++) {
                        unsigned r0 = __shfl_sync(~0u, rec, j);
                        uint2 va = *(const uint2*)(xg + (size_t)(r0 & 0xFFFFu)*K + lane*4);
                        float nrm = rec_norm(r0);
                        float2 f0 = __half22float2(*(__half2*)&va.x);
                        float2 f1 = __half22float2(*(__half2*)&va.y);
                        a0 = fmaf(f0.x, nrm, a0); a1 = fmaf(f0.y, nrm, a1);
                        a2 = fmaf(f1.x, nrm, a2); a3 = fmaf(f1.y, nrm, a3);
                    }
                }
                uint2 o;
                *(__half2*)&o.x = __floats2half2_rn(a0, a1);
                *(__half2*)&o.y = __floats2half2_rn(a2, a3);
                *(uint2*)(As + rl*AS + lane*4) = o;
            }
        } else {
            if (K == FIN) *(__half2*)(As + rl*AS + lane*2) = __floats2half2_rn(0.f, 0.f);
            else *(uint2*)(As + rl*AS + lane*4) = make_uint2(0u, 0u);
        }
    }
    __syncthreads();

    // mma phase
    float d[16][4];
#pragma unroll
    for (int t = 0; t < 16; t++) {
        d[t][0] = 0.f; d[t][1] = 0.f; d[t][2] = 0.f; d[t][3] = 0.f;
    }
    unsigned a_sm = cvta_sm(As);
    unsigned w_sm = cvta_sm(Ws);
    int arow = wid*16 + (lane & 15);
    int asel = (lane >> 4) * 8;
    int krow = lane & 15;
    for (int kk = 0; kk < K/16; kk++) {
        unsigned a0, a1, a2, a3;
        ldmx4(a0, a1, a2, a3, a_sm + (unsigned)(arow*AS + kk*16 + asel)*2u);
#pragma unroll
        for (int nt = 0; nt < 8; nt++) {
            unsigned b0, b1, b2, b3;
            ldmx4t(b0, b1, b2, b3, w_sm + (unsigned)((kk*16 + krow)*WS + nt*16 + asel)*2u);
            mma16816(d[2*nt],   a0, a1, a2, a3, b0, b1);
            mma16816(d[2*nt+1], a0, a1, a2, a3, b2, b3);
        }
    }

    // epilogue: bias + relu -> fp16
    int gq = lane >> 2, tq = lane & 3;
    int row0 = base + wid*16 + gq;
    int row1 = row0 + 8;
#pragma unroll
    for (int nt = 0; nt < 16; nt++) {
        int c0 = nt*8 + tq*2;
        float2 bc = *(const float2*)(bias + c0);
        float v00 = fmaxf(d[nt][0] + bc.x, 0.f);
        float v01 = fmaxf(d[nt][1] + bc.y, 0.f);
        float v10 = fmaxf(d[nt][2] + bc.x, 0.f);
        float v11 = fmaxf(d[nt][3] + bc.y, 0.f);
        __half2 h0 = __floats2half2_rn(v00, v01);
        __half2 h1 = __floats2half2_rn(v10, v11);
        if (row0 < GN) *(unsigned*)(hout + (size_t)row0*HH + c0) = *(unsigned*)&h0;
        if (row1 < GN) *(unsigned*)(hout + (size_t)row1*HH + c0) = *(unsigned*)&h1;
    }
}

// ---------------- pooling --------------------------------------------------------
__global__ void __launch_bounds__(256) k_pool2() {
    int g = blockIdx.x / BB, b = blockIdx.x % BB;
    int s = g_bstart[g*(BB+1) + b], e = g_bstart[g*(BB+1) + b + 1];
    int cnt = e - s;
    int tid = threadIdx.x;
    int cg = tid & 31, r0 = tid >> 5;
    float4 acc = make_float4(0.f, 0.f, 0.f, 0.f);
    const uint2* a2 = (const uint2*)(g_a2h + (size_t)g*NN*HH);
    for (int n = s + r0; n < e; n += 8) {
        uint2 v = a2[(size_t)n*32 + cg];
        __half2 h0 = *(__half2*)&v.x, h1 = *(__half2*)&v.y;
        float2 f0 = __half22float2(h0), f1 = __half22float2(h1);
        acc.x += f0.x; acc.y += f0.y; acc.z += f1.x; acc.w += f1.y;
    }
    __shared__ float4 sacc[256];
    sacc[tid] = acc;
    __syncthreads();
    if (tid < 32) {
        float4 t = sacc[tid];
#pragma unroll
        for (int r = 1; r < 8; r++) {
            float4 o = sacc[tid + 32*r];
            t.x += o.x; t.y += o.y; t.z += o.z; t.w += o.w;
        }
        float inv = (cnt > 0) ? 1.0f/(float)cnt : 0.0f;
        *(float4*)(g_emb + (size_t)blockIdx.x*HH + tid*4) =
            make_float4(t.x*inv, t.y*inv, t.z*inv, t.w*inv);
    }
}

// ---------------- fused attention (one block per batch-bucket b) -------------------
__global__ void __launch_bounds__(384) k_attall(const float* __restrict__ ipw,
        const float* __restrict__ ipb, const float* __restrict__ opw,
        const float* __restrict__ opb) {
    __shared__ float emb[GG][HH];
    __shared__ float qkv[3][GG][HH];
    __shared__ float sc[NHEADS][GG][GG];
    __shared__ float att[GG][HH];
    int b = blockIdx.x, tid = threadIdx.x;
    for (int i = tid; i < GG*HH; i += 384) {
        int g = i >> 7, c = i & 127;
        emb[g][c] = g_emb[(g*BB + b)*HH + c];
    }
    __syncthreads();
#pragma unroll
    for (int t = 0; t < 4; t++) {
        int o = tid + t*384;
        int sec = o / 512, rem = o - sec*512, g = rem >> 7, i = rem & 127;
        const float* wrow = ipw + (size_t)(sec*HH + i)*HH;
        float s = ipb[sec*HH + i];
#pragma unroll 8
        for (int j = 0; j < HH; j++) s += emb[g][j]*wrow[j];
        qkv[sec][g][i] = s;
    }
    __syncthreads();
    if (tid < 128) {
        int h = tid >> 4, g = (tid >> 2) & 3, k = tid & 3;
        float s = 0.f;
#pragma unroll
        for (int dd = 0; dd < HD; dd++) s += qkv[0][g][h*HD + dd]*qkv[1][k][h*HD + dd];
        sc[h][g][k] = s*0.25f;
    }
    __syncthreads();
    for (int o = tid; o < GG*HH; o += 384) {
        int g = o >> 7, i = o & 127, h = i >> 4;
        float s0 = sc[h][g][0], s1 = sc[h][g][1], s2 = sc[h][g][2], s3 = sc[h][g][3];
        float m = fmaxf(fmaxf(s0, s1), fmaxf(s2, s3));
        float e0 = expf(s0 - m), e1 = expf(s1 - m), e2 = expf(s2 - m), e3 = expf(s3 - m);
        float inv = 1.f/(e0 + e1 + e2 + e3);
        att[g][i] = (e0*qkv[2][0][i] + e1*qkv[2][1][i] + e2*qkv[2][2][i] + e3*qkv[2][3][i])*inv;
    }
    __syncthreads();
    for (int o = tid; o < GG*HH; o += 384) {
        int g = o >> 7, i = o & 127;
        const float* wrow = opw + (size_t)i*HH;
        float s = opb[i];
#pragma unroll 8
        for (int j = 0; j < HH; j++) s += att[g][j]*wrow[j];
        atomicAdd(&g_pooled[g*HH + i], s*(1.0f/BB));
    }
}

// ---------------- final linear ------------------------------------------------------
__global__ void k_final(const float* __restrict__ lw, const float* __restrict__ lb,
                        float* __restrict__ out) {
    __shared__ float ps[GG*HH];
    int tid = threadIdx.x;
    for (int i = tid; i < GG*HH; i += 256) ps[i] = g_pooled[i];
    __syncthreads();
    int n = blockIdx.x*8 + (tid >> 5);
    if (n >= NNODES) return;
    int lane = tid & 31;
    float4 lv = *(const float4*)(lw + (size_t)n*HH + lane*4);
    float d[GG];
#pragma unroll
    for (int g = 0; g < GG; g++) {
        const float* pg = ps + g*HH + lane*4;
        d[g] = lv.x*pg[0] + lv.y*pg[1] + lv.z*pg[2] + lv.w*pg[3];
    }
#pragma unroll
    for (int g = 0; g < GG; g++)
        for (int off = 16; off; off >>= 1)
            d[g] += __shfl_xor_sync(~0u, d[g], off);
    if (lane == 0) {
        float bn = lb[n];
#pragma unroll
        for (int g = 0; g < GG; g++)
            out[(size_t)g*NNODES + n] = (d[g] + bn)*60.0f + 50.0f;
    }
}

// ---------------- launch -------------------------------------------------------------
extern "C" void kernel_launch(void* const* d_in, const int* in_sizes, int n_in,
                              void* d_out, int out_size) {
    const float* x   = (const float*)d_in[0];
    const int*   ei  = (const int*)  d_in[1];
    const int*   bat = (const int*)  d_in[2];
    const float* W1  = (const float*)d_in[3];
    const float* b1  = (const float*)d_in[4];
    const float* W2  = (const float*)d_in[5];
    const float* b2  = (const float*)d_in[6];
    const float* ipw = (const float*)d_in[7];
    const float* ipb = (const float*)d_in[8];
    const float* opw = (const float*)d_in[9];
    const float* opb = (const float*)d_in[10];
    const float* lw  = (const float*)d_in[11];
    const float* lb  = (const float*)d_in[12];
    float* out = (float*)d_out;

    __half *p_xh, *p_a1h, *p_a2h, *p_w1h, *p_w2h;
    int *p_degi;
    cudaGetSymbolAddress((void**)&p_xh,   g_xh);
    cudaGetSymbolAddress((void**)&p_a1h,  g_a1h);
    cudaGetSymbolAddress((void**)&p_a2h,  g_a2h);
    cudaGetSymbolAddress((void**)&p_w1h,  g_w1h);
    cudaGetSymbolAddress((void**)&p_w2h,  g_w2h);
    cudaGetSymbolAddress((void**)&p_degi, g_degi);

    const int smem1 = (128*(FIN+8) + FIN*(HH+8))*2;   // 35840 B
    const int smem2 = (128*(HH+8) + HH*(HH+8))*2;     // 69632 B
    cudaFuncSetAttribute(k_fused<FIN>, cudaFuncAttributeMaxDynamicSharedMemorySize, smem1);
    cudaFuncSetAttribute(k_fused<HH>,  cudaFuncAttributeMaxDynamicSharedMemorySize, smem2);

    // independent conversions + misc first
    cudaMemsetAsync(p_degi, 0, GN*sizeof(int), 0);
    k_xcvt<<<(GN*FIN/8 + 255)/256, 256>>>(x);
    k_misc<<<(HH*HH + 255)/256, 256>>>(W1, W2, bat);

    // CSR build
    k_count<<<(GE+255)/256, 256>>>(ei);
    k_scan1<<<GG*TILES, 1024>>>();
    k_scan3m<<<GG*TILES, 1024>>>();
    k_fill<<<(GE+255)/256, 256>>>(ei);

    // layer 1 fused: gather x + matmul + relu -> a1 (fp16)
    k_fused<FIN><<<(GN+127)/128, 256, smem1>>>(p_xh, p_w1h, b1, p_a1h);
    // layer 2 fused: gather a1 + matmul + relu -> a2 (fp16)
    k_fused<HH><<<(GN+127)/128, 256, smem2>>>(p_a1h, p_w2h, b2, p_a2h);

    // mean pooling per (graph, bucket)
    k_pool2<<<GG*BB, 256>>>();

    // fused attention + projections + mean over B
    k_attall<<<BB, 384>>>(ipw, ipb, opw, opb);

    // final linear + affine
    k_final<<<(NNODES+7)/8, 256>>>(lw, lb, out);
}

// round 11
// speedup vs baseline: 1.0863x; 1.0863x over previous
#include <cuda_runtime.h>
#include <cuda_fp16.h>
#include <stdint.h>
#include <math.h>

#define GG 4
#define NN 50000
#define EE 800000
#define BB 32
#define FIN 64
#define HH 128
#define NHEADS 8
#define HD 16
#define GN (GG*NN)
#define GE (GG*EE)
#define GBH (GG*BB*HH)
#define NNODES 50000
#define TILES 49   // ceil(NN/1024)

// ---------------- scratch (device globals; no allocation allowed) -------------
__device__ __half g_xh[(size_t)GN*FIN];     // fp16 copy of x
__device__ __half g_a1h[(size_t)GN*HH];     // relu(layer1) fp16
__device__ __half g_a2h[(size_t)GN*HH];     // relu(layer2) fp16
__device__ __half g_w1h[FIN*HH];
__device__ __half g_w2h[HH*HH];
__device__ int   g_degi[GN];
__device__ float g_dinv[GN];
__device__ int   g_off[GG*(NN+1)];
__device__ int   g_cur[GN];
__device__ int   g_tsum[GG*TILES];
__device__ unsigned g_csr[(size_t)GE];      // packed {norm-fp16:hi16, row-u16:lo16}
__device__ int   g_bstart[GG*(BB+1)];
__device__ float g_emb[GBH];                // pooled means
__device__ float g_pooled[GG*HH];

// ---------------- mma / ldmatrix helpers ------------------------------------------
__device__ __forceinline__ unsigned cvta_sm(const void* p) {
    return (unsigned)__cvta_generic_to_shared(p);
}
__device__ __forceinline__ void ldmx4(unsigned& r0, unsigned& r1, unsigned& r2, unsigned& r3, unsigned a) {
    asm volatile("ldmatrix.sync.aligned.m8n8.x4.shared.b16 {%0,%1,%2,%3},[%4];"
        : "=r"(r0), "=r"(r1), "=r"(r2), "=r"(r3) : "r"(a));
}
__device__ __forceinline__ void ldmx4t(unsigned& r0, unsigned& r1, unsigned& r2, unsigned& r3, unsigned a) {
    asm volatile("ldmatrix.sync.aligned.m8n8.x4.trans.shared.b16 {%0,%1,%2,%3},[%4];"
        : "=r"(r0), "=r"(r1), "=r"(r2), "=r"(r3) : "r"(a));
}
__device__ __forceinline__ void mma16816(float* d, unsigned a0, unsigned a1, unsigned a2, unsigned a3,
                                         unsigned b0, unsigned b1) {
    asm volatile("mma.sync.aligned.m16n8k16.row.col.f32.f16.f16.f32 "
        "{%0,%1,%2,%3},{%4,%5,%6,%7},{%8,%9},{%0,%1,%2,%3};"
        : "+f"(d[0]), "+f"(d[1]), "+f"(d[2]), "+f"(d[3])
        : "r"(a0), "r"(a1), "r"(a2), "r"(a3), "r"(b0), "r"(b1));
}
__device__ __forceinline__ float rec_norm(unsigned r) {
    return __half2float(__ushort_as_half((unsigned short)(r >> 16)));
}

// ---------------- conversions ------------------------------------------------------
__global__ void k_xcvt(const float* __restrict__ x) {
    size_t i = (size_t)blockIdx.x*blockDim.x + threadIdx.x;
    if (i >= (size_t)GN*FIN/8) return;
    const float4* xs = (const float4*)x;
    float4 f0 = xs[2*i], f1 = xs[2*i+1];
    __half2 h0 = __floats2half2_rn(f0.x, f0.y);
    __half2 h1 = __floats2half2_rn(f0.z, f0.w);
    __half2 h2 = __floats2half2_rn(f1.x, f1.y);
    __half2 h3 = __floats2half2_rn(f1.z, f1.w);
    uint4 o = make_uint4(*(unsigned*)&h0, *(unsigned*)&h1, *(unsigned*)&h2, *(unsigned*)&h3);
    ((uint4*)g_xh)[i] = o;
}
// merged: W conversions + pooled zero + bucket bounds
__global__ void k_misc(const float* __restrict__ W1, const float* __restrict__ W2,
                       const int* __restrict__ batch) {
    int i = blockIdx.x*blockDim.x + threadIdx.x;
    if (i < FIN*HH) g_w1h[i] = __float2half_rn(W1[i]);
    if (i < HH*HH)  g_w2h[i] = __float2half_rn(W2[i]);
    if (i < GG*HH)  g_pooled[i] = 0.f;
    if (i < GG*BB) {
        int g = i >> 5, b = i & 31;
        const int* bt = batch + (size_t)g*NN;
        int lo = 0, hi = NN;
        while (lo < hi) {
            int mid = (lo + hi) >> 1;
            if (bt[mid] < b) lo = mid + 1; else hi = mid;
        }
        g_bstart[g*(BB+1) + b] = lo;
        if (b == 0) g_bstart[g*(BB+1) + BB] = NN;
    }
}

// ---------------- CSR build ------------------------------------------------------
__global__ void k_count(const int* __restrict__ ei) {
    int idx = blockIdx.x*blockDim.x + threadIdx.x;
    if (idx >= GE) return;
    int g = idx / EE, e = idx - g*EE;
    int col = ei[(size_t)g*2*EE + EE + e];
    atomicAdd(&g_degi[g*NN + col], 1);
}
__global__ void k_scan1() {
    int g = blockIdx.x / TILES, t = blockIdx.x % TILES;
    int tid = threadIdx.x, lane = tid & 31, wid = tid >> 5;
    __shared__ int wtot[32];
    int i = t*1024 + tid;
    int c = (i < NN) ? g_degi[g*NN + i] : 0;
    int v = c;
#pragma unroll
    for (int o = 1; o < 32; o <<= 1) {
        int u = __shfl_up_sync(~0u, v, o);
        if (lane >= o) v += u;
    }
    if (lane == 31) wtot[wid] = v;
    __syncthreads();
    if (wid == 0) {
        int w2 = wtot[lane];
#pragma unroll
        for (int o = 1; o < 32; o <<= 1) {
            int u = __shfl_up_sync(~0u, w2, o);
            if (lane >= o) w2 += u;
        }
        wtot[lane] = w2;
    }
    __syncthreads();
    int excl = (wid > 0 ? wtot[wid-1] : 0) + v - c;
    if (i < NN) {
        g_off[g*(NN+1) + i] = excl;
        g_dinv[g*NN + i] = rsqrtf((float)(c + 1));
    }
    if (tid == 0) g_tsum[blockIdx.x] = wtot[31];
}
// scan2+scan3 merged: each block recomputes its tile base from g_tsum
__global__ void k_scan3m() {
    int g = blockIdx.x / TILES, t = blockIdx.x % TILES;
    int tid = threadIdx.x;
    __shared__ int part[64];
    __shared__ int sbase;
    if (tid < 64) part[tid] = (tid < t) ? g_tsum[g*TILES + tid] : 0;
    __syncthreads();
    if (tid < 32) {
        int v = part[tid] + part[tid + 32];
#pragma unroll
        for (int o = 16; o; o >>= 1) v += __shfl_xor_sync(~0u, v, o);
        if (tid == 0) sbase = v;
    }
    __syncthreads();
    int i = t*1024 + tid;
    if (i < NN) {
        int o = g_off[g*(NN+1) + i] + sbase;
        g_off[g*(NN+1) + i] = o;
        g_cur[g*NN + i] = o;
    }
    if (blockIdx.x == 0 && tid < GG)
        g_off[tid*(NN+1) + NN] = EE;
}
__global__ void k_fill(const int* __restrict__ ei) {
    int idx = blockIdx.x*blockDim.x + threadIdx.x;
    if (idx >= GE) return;
    int g = idx / EE, e = idx - g*EE;
    const int* bp = ei + (size_t)g*2*EE;
    int row = bp[e], col = bp[EE + e];
    float norm = g_dinv[g*NN + row] * g_dinv[g*NN + col];
    unsigned rec = (unsigned)row |
        ((unsigned)__half_as_ushort(__float2half_rn(norm)) << 16);
    int pos = atomicAdd(&g_cur[g*NN + col], 1);
    g_csr[(size_t)g*EE + pos] = rec;
}

// ---------------- fused gather + tensor-core matmul per layer ----------------------
// relu( (D^-1/2 A D^-1/2 + selfloop) src @ W + b ) -> fp16 hout
// 256 threads; block handles 128 nodes; warp w gathers nodes w*16..w*16+15 into smem,
// then the block does a 128x128 mma.  (R7 champion inner loop — do not touch.)
template<int K>
__global__ void __launch_bounds__(256) k_fused(const __half* __restrict__ src,
        const __half* __restrict__ Wh, const float* __restrict__ bias,
        __half* __restrict__ hout) {
    constexpr int AS = K + 8;      // padded A row (halfs)
    constexpr int WS = HH + 8;     // 136
    extern __shared__ __half smh[];
    __half* As = smh;              // 128 * AS
    __half* Ws = smh + 128*AS;     // K * WS
    int tid = threadIdx.x, wid = tid >> 5, lane = tid & 31;
    int base = blockIdx.x * 128;

    // load W tile
    for (int idx = tid; idx < K*16; idx += 256) {
        int r = idx >> 4, c8 = (idx & 15) << 3;
        *(uint4*)(Ws + r*WS + c8) = *(const uint4*)(Wh + r*HH + c8);
    }

    // gather phase: warp handles 16 local rows
    for (int t = 0; t < 16; t++) {
        int rl = wid*16 + t;
        int w = base + rl;
        if (w < GN) {
            int g = w / NN, n = w - g*NN;
            const __half* xg = src + (size_t)g*NN*K;
            float di = g_dinv[w], d2 = di*di;
            int s = g_off[g*(NN+1) + n], e2 = g_off[g*(NN+1) + n + 1];
            const unsigned* cs = g_csr + (size_t)g*EE;
            if (K == FIN) {
                float a0, a1;
                {
                    float2 f = __half22float2(*(const __half2*)(xg + (size_t)n*K + lane*2));
                    a0 = f.x*d2; a1 = f.y*d2;
                }
                int i = s;
                for (; i + 1 < e2; i += 2) {
                    unsigned r0 = __ldg(&cs[i]), r1 = __ldg(&cs[i+1]);
                    float n0 = rec_norm(r0), n1 = rec_norm(r1);
                    __half2 ha = *(const __half2*)(xg + (size_t)(r0 & 0xFFFFu)*K + lane*2);
                    __half2 hb = *(const __half2*)(xg + (size_t)(r1 & 0xFFFFu)*K + lane*2);
                    float2 fa = __half22float2(ha), fb = __half22float2(hb);
                    a0 = fmaf(fa.x, n0, fmaf(fb.x, n1, a0));
                    a1 = fmaf(fa.y, n0, fmaf(fb.y, n1, a1));
                }
                if (i < e2) {
                    unsigned r0 = __ldg(&cs[i]);
                    float n0 = rec_norm(r0);
                    __half2 ha = *(const __half2*)(xg + (size_t)(r0 & 0xFFFFu)*K + lane*2);
                    float2 fa = __half22float2(ha);
                    a0 = fmaf(fa.x, n0, a0);
                    a1 = fmaf(fa.y, n0, a1);
                }
                *(__half2*)(As + rl*AS + lane*2) = __floats2half2_rn(a0, a1);
            } else {
                float a0, a1, a2, a3;
                {
                    uint2 hv = *(const uint2*)(xg + (size_t)n*K + lane*4);
                    float2 f0 = __half22float2(*(__half2*)&hv.x);
                    float2 f1 = __half22float2(*(__half2*)&hv.y);
                    a0 = f0.x*d2; a1 = f0.y*d2; a2 = f1.x*d2; a3 = f1.y*d2;
                }
                int i = s;
                for (; i + 1 < e2; i += 2) {
                    unsigned r0 = __ldg(&cs[i]), r1 = __ldg(&cs[i+1]);
                    float n0 = rec_norm(r0), n1 = rec_norm(r1);
                    uint2 va = *(const uint2*)(xg + (size_t)(r0 & 0xFFFFu)*K + lane*4);
                    uint2 vb = *(const uint2*)(xg + (size_t)(r1 & 0xFFFFu)*K + lane*4);
                    float2 fa0 = __half22float2(*(__half2*)&va.x);
                    float2 fa1 = __half22float2(*(__half2*)&va.y);
                    float2 fb0 = __half22float2(*(__half2*)&vb.x);
                    float2 fb1 = __half22float2(*(__half2*)&vb.y);
                    a0 = fmaf(fa0.x, n0, fmaf(fb0.x, n1, a0));
                    a1 = fmaf(fa0.y, n0, fmaf(fb0.y, n1, a1));
                    a2 = fmaf(fa1.x, n0, fmaf(fb1.x, n1, a2));
                    a3 = fmaf(fa1.y, n0, fmaf(fb1.y, n1, a3));
                }
                if (i < e2) {
                    unsigned r0 = __ldg(&cs[i]);
                    float n0 = rec_norm(r0);
                    uint2 va = *(const uint2*)(xg + (size_t)(r0 & 0xFFFFu)*K + lane*4);
                    float2 fa0 = __half22float2(*(__half2*)&va.x);
                    float2 fa1 = __half22float2(*(__half2*)&va.y);
                    a0 = fmaf(fa0.x, n0, a0);
                    a1 = fmaf(fa0.y, n0, a1);
                    a2 = fmaf(fa1.x, n0, a2);
                    a3 = fmaf(fa1.y, n0, a3);
                }
                uint2 o;
                *(__half2*)&o.x = __floats2half2_rn(a0, a1);
                *(__half2*)&o.y = __floats2half2_rn(a2, a3);
                *(uint2*)(As + rl*AS + lane*4) = o;
            }
        } else {
            if (K == FIN) *(__half2*)(As + rl*AS + lane*2) = __floats2half2_rn(0.f, 0.f);
            else *(uint2*)(As + rl*AS + lane*4) = make_uint2(0u, 0u);
        }
    }
    __syncthreads();

    // mma phase
    float d[16][4];
#pragma unroll
    for (int t = 0; t < 16; t++) {
        d[t][0] = 0.f; d[t][1] = 0.f; d[t][2] = 0.f; d[t][3] = 0.f;
    }
    unsigned a_sm = cvta_sm(As);
    unsigned w_sm = cvta_sm(Ws);
    int arow = wid*16 + (lane & 15);
    int asel = (lane >> 4) * 8;
    int krow = lane & 15;
    for (int kk = 0; kk < K/16; kk++) {
        unsigned a0, a1, a2, a3;
        ldmx4(a0, a1, a2, a3, a_sm + (unsigned)(arow*AS + kk*16 + asel)*2u);
#pragma unroll
        for (int nt = 0; nt < 8; nt++) {
            unsigned b0, b1, b2, b3;
            ldmx4t(b0, b1, b2, b3, w_sm + (unsigned)((kk*16 + krow)*WS + nt*16 + asel)*2u);
            mma16816(d[2*nt],   a0, a1, a2, a3, b0, b1);
            mma16816(d[2*nt+1], a0, a1, a2, a3, b2, b3);
        }
    }

    // epilogue: bias + relu -> fp16
    int gq = lane >> 2, tq = lane & 3;
    int row0 = base + wid*16 + gq;
    int row1 = row0 + 8;
#pragma unroll
    for (int nt = 0; nt < 16; nt++) {
        int c0 = nt*8 + tq*2;
        float2 bc = *(const float2*)(bias + c0);
        float v00 = fmaxf(d[nt][0] + bc.x, 0.f);
        float v01 = fmaxf(d[nt][1] + bc.y, 0.f);
        float v10 = fmaxf(d[nt][2] + bc.x, 0.f);
        float v11 = fmaxf(d[nt][3] + bc.y, 0.f);
        __half2 h0 = __floats2half2_rn(v00, v01);
        __half2 h1 = __floats2half2_rn(v10, v11);
        if (row0 < GN) *(unsigned*)(hout + (size_t)row0*HH + c0) = *(unsigned*)&h0;
        if (row1 < GN) *(unsigned*)(hout + (size_t)row1*HH + c0) = *(unsigned*)&h1;
    }
}

// ---------------- pooling --------------------------------------------------------
__global__ void __launch_bounds__(256) k_pool2() {
    int g = blockIdx.x / BB, b = blockIdx.x % BB;
    int s = g_bstart[g*(BB+1) + b], e = g_bstart[g*(BB+1) + b + 1];
    int cnt = e - s;
    int tid = threadIdx.x;
    int cg = tid & 31, r0 = tid >> 5;
    float4 acc = make_float4(0.f, 0.f, 0.f, 0.f);
    const uint2* a2 = (const uint2*)(g_a2h + (size_t)g*NN*HH);
    for (int n = s + r0; n < e; n += 8) {
        uint2 v = a2[(size_t)n*32 + cg];
        __half2 h0 = *(__half2*)&v.x, h1 = *(__half2*)&v.y;
        float2 f0 = __half22float2(h0), f1 = __half22float2(h1);
        acc.x += f0.x; acc.y += f0.y; acc.z += f1.x; acc.w += f1.y;
    }
    __shared__ float4 sacc[256];
    sacc[tid] = acc;
    __syncthreads();
    if (tid < 32) {
        float4 t = sacc[tid];
#pragma unroll
        for (int r = 1; r < 8; r++) {
            float4 o = sacc[tid + 32*r];
            t.x += o.x; t.y += o.y; t.z += o.z; t.w += o.w;
        }
        float inv = (cnt > 0) ? 1.0f/(float)cnt : 0.0f;
        *(float4*)(g_emb + (size_t)blockIdx.x*HH + tid*4) =
            make_float4(t.x*inv, t.y*inv, t.z*inv, t.w*inv);
    }
}

// ---------------- fused attention (one block per batch-bucket b) -------------------
__global__ void __launch_bounds__(384) k_attall(const float* __restrict__ ipw,
        const float* __restrict__ ipb, const float* __restrict__ opw,
        const float* __restrict__ opb) {
    __shared__ float emb[GG][HH];
    __shared__ float qkv[3][GG][HH];
    __shared__ float sc[NHEADS][GG][GG];
    __shared__ float att[GG][HH];
    int b = blockIdx.x, tid = threadIdx.x;
    for (int i = tid; i < GG*HH; i += 384) {
        int g = i >> 7, c = i & 127;
        emb[g][c] = g_emb[(g*BB + b)*HH + c];
    }
    __syncthreads();
#pragma unroll
    for (int t = 0; t < 4; t++) {
        int o = tid + t*384;
        int sec = o / 512, rem = o - sec*512, g = rem >> 7, i = rem & 127;
        const float* wrow = ipw + (size_t)(sec*HH + i)*HH;
        float s = ipb[sec*HH + i];
#pragma unroll 8
        for (int j = 0; j < HH; j++) s += emb[g][j]*wrow[j];
        qkv[sec][g][i] = s;
    }
    __syncthreads();
    if (tid < 128) {
        int h = tid >> 4, g = (tid >> 2) & 3, k = tid & 3;
        float s = 0.f;
#pragma unroll
        for (int dd = 0; dd < HD; dd++) s += qkv[0][g][h*HD + dd]*qkv[1][k][h*HD + dd];
        sc[h][g][k] = s*0.25f;
    }
    __syncthreads();
    for (int o = tid; o < GG*HH; o += 384) {
        int g = o >> 7, i = o & 127, h = i >> 4;
        float s0 = sc[h][g][0], s1 = sc[h][g][1], s2 = sc[h][g][2], s3 = sc[h][g][3];
        float m = fmaxf(fmaxf(s0, s1), fmaxf(s2, s3));
        float e0 = expf(s0 - m), e1 = expf(s1 - m), e2 = expf(s2 - m), e3 = expf(s3 - m);
        float inv = 1.f/(e0 + e1 + e2 + e3);
        att[g][i] = (e0*qkv[2][0][i] + e1*qkv[2][1][i] + e2*qkv[2][2][i] + e3*qkv[2][3][i])*inv;
    }
    __syncthreads();
    for (int o = tid; o < GG*HH; o += 384) {
        int g = o >> 7, i = o & 127;
        const float* wrow = opw + (size_t)i*HH;
        float s = opb[i];
#pragma unroll 8
        for (int j = 0; j < HH; j++) s += att[g][j]*wrow[j];
        atomicAdd(&g_pooled[g*HH + i], s*(1.0f/BB));
    }
}

// ---------------- final linear ------------------------------------------------------
__global__ void k_final(const float* __restrict__ lw, const float* __restrict__ lb,
                        float* __restrict__ out) {
    __shared__ float ps[GG*HH];
    int tid = threadIdx.x;
    for (int i = tid; i < GG*HH; i += 256) ps[i] = g_pooled[i];
    __syncthreads();
    int n = blockIdx.x*8 + (tid >> 5);
    if (n >= NNODES) return;
    int lane = tid & 31;
    float4 lv = *(const float4*)(lw + (size_t)n*HH + lane*4);
    float d[GG];
#pragma unroll
    for (int g = 0; g < GG; g++) {
        const float* pg = ps + g*HH + lane*4;
        d[g] = lv.x*pg[0] + lv.y*pg[1] + lv.z*pg[2] + lv.w*pg[3];
    }
#pragma unroll
    for (int g = 0; g < GG; g++)
        for (int off = 16; off; off >>= 1)
            d[g] += __shfl_xor_sync(~0u, d[g], off);
    if (lane == 0) {
        float bn = lb[n];
#pragma unroll
        for (int g = 0; g < GG; g++)
            out[(size_t)g*NNODES + n] = (d[g] + bn)*60.0f + 50.0f;
    }
}

// ---------------- launch -------------------------------------------------------------
extern "C" void kernel_launch(void* const* d_in, const int* in_sizes, int n_in,
                              void* d_out, int out_size) {
    const float* x   = (const float*)d_in[0];
    const int*   ei  = (const int*)  d_in[1];
    const int*   bat = (const int*)  d_in[2];
    const float* W1  = (const float*)d_in[3];
    const float* b1  = (const float*)d_in[4];
    const float* W2  = (const float*)d_in[5];
    const float* b2  = (const float*)d_in[6];
    const float* ipw = (const float*)d_in[7];
    const float* ipb = (const float*)d_in[8];
    const float* opw = (const float*)d_in[9];
    const float* opb = (const float*)d_in[10];
    const float* lw  = (const float*)d_in[11];
    const float* lb  = (const float*)d_in[12];
    float* out = (float*)d_out;

    __half *p_xh, *p_a1h, *p_a2h, *p_w1h, *p_w2h;
    int *p_degi;
    cudaGetSymbolAddress((void**)&p_xh,   g_xh);
    cudaGetSymbolAddress((void**)&p_a1h,  g_a1h);
    cudaGetSymbolAddress((void**)&p_a2h,  g_a2h);
    cudaGetSymbolAddress((void**)&p_w1h,  g_w1h);
    cudaGetSymbolAddress((void**)&p_w2h,  g_w2h);
    cudaGetSymbolAddress((void**)&p_degi, g_degi);

    const int smem1 = (128*(FIN+8) + FIN*(HH+8))*2;   // 35840 B
    const int smem2 = (128*(HH+8) + HH*(HH+8))*2;     // 69632 B
    cudaFuncSetAttribute(k_fused<FIN>, cudaFuncAttributeMaxDynamicSharedMemorySize, smem1);
    cudaFuncSetAttribute(k_fused<HH>,  cudaFuncAttributeMaxDynamicSharedMemorySize, smem2);

    // independent conversions + misc first
    cudaMemsetAsync(p_degi, 0, GN*sizeof(int), 0);
    k_xcvt<<<(GN*FIN/8 + 255)/256, 256>>>(x);
    k_misc<<<(HH*HH + 255)/256, 256>>>(W1, W2, bat);

    // CSR build
    k_count<<<(GE+255)/256, 256>>>(ei);
    k_scan1<<<GG*TILES, 1024>>>();
    k_scan3m<<<GG*TILES, 1024>>>();
    k_fill<<<(GE+255)/256, 256>>>(ei);

    // layer 1 fused: gather x + matmul + relu -> a1 (fp16)
    k_fused<FIN><<<(GN+127)/128, 256, smem1>>>(p_xh, p_w1h, b1, p_a1h);
    // layer 2 fused: gather a1 + matmul + relu -> a2 (fp16)
    k_fused<HH><<<(GN+127)/128, 256, smem2>>>(p_a1h, p_w2h, b2, p_a2h);

    // mean pooling per (graph, bucket)
    k_pool2<<<GG*BB, 256>>>();

    // fused attention + projections + mean over B
    k_attall<<<BB, 384>>>(ipw, ipb, opw, opb);

    // final linear + affine
    k_final<<<(NNODES+7)/8, 256>>>(lw, lb, out);
}

// round 12
// speedup vs baseline: 1.1544x; 1.0627x over previous
#include <cuda_runtime.h>
#include <cuda_fp16.h>
#include <stdint.h>
#include <math.h>

#define GG 4
#define NN 50000
#define EE 800000
#define BB 32
#define FIN 64
#define HH 128
#define NHEADS 8
#define HD 16
#define GN (GG*NN)
#define GE (GG*EE)
#define GBH (GG*BB*HH)
#define NNODES 50000
#define TILES 49   // ceil(NN/1024)

// ---------------- scratch (device globals; no allocation allowed) -------------
__device__ __half g_xh[(size_t)GN*FIN];     // fp16 copy of x
__device__ __half g_a1h[(size_t)GN*HH];     // relu(layer1) fp16
__device__ __half g_a2h[(size_t)GN*HH];     // relu(layer2) fp16
__device__ __half g_w1h[FIN*HH];
__device__ __half g_w2h[HH*HH];
__device__ int   g_degi[GN];
__device__ float g_dinv[GN];
__device__ int   g_off[GG*(NN+1)];
__device__ int   g_cur[GN];
__device__ int   g_tsum[GG*TILES];
__device__ unsigned g_csr[(size_t)GE];      // packed {norm-fp16:hi16, row-u16:lo16}
__device__ int   g_bstart[GG*(BB+1)];
__device__ float g_emb[GBH];                // pooled means
__device__ float g_pooled[GG*HH];

// ---------------- mma / ldmatrix helpers ------------------------------------------
__device__ __forceinline__ unsigned cvta_sm(const void* p) {
    return (unsigned)__cvta_generic_to_shared(p);
}
__device__ __forceinline__ void ldmx4(unsigned& r0, unsigned& r1, unsigned& r2, unsigned& r3, unsigned a) {
    asm volatile("ldmatrix.sync.aligned.m8n8.x4.shared.b16 {%0,%1,%2,%3},[%4];"
        : "=r"(r0), "=r"(r1), "=r"(r2), "=r"(r3) : "r"(a));
}
__device__ __forceinline__ void ldmx4t(unsigned& r0, unsigned& r1, unsigned& r2, unsigned& r3, unsigned a) {
    asm volatile("ldmatrix.sync.aligned.m8n8.x4.trans.shared.b16 {%0,%1,%2,%3},[%4];"
        : "=r"(r0), "=r"(r1), "=r"(r2), "=r"(r3) : "r"(a));
}
__device__ __forceinline__ void mma16816(float* d, unsigned a0, unsigned a1, unsigned a2, unsigned a3,
                                         unsigned b0, unsigned b1) {
    asm volatile("mma.sync.aligned.m16n8k16.row.col.f32.f16.f16.f32 "
        "{%0,%1,%2,%3},{%4,%5,%6,%7},{%8,%9},{%0,%1,%2,%3};"
        : "+f"(d[0]), "+f"(d[1]), "+f"(d[2]), "+f"(d[3])
        : "r"(a0), "r"(a1), "r"(a2), "r"(a3), "r"(b0), "r"(b1));
}
__device__ __forceinline__ float rec_norm(unsigned r) {
    return __half2float(__ushort_as_half((unsigned short)(r >> 16)));
}

// ---------------- conversions ------------------------------------------------------
__global__ void k_xcvt(const float* __restrict__ x) {
    size_t i = (size_t)blockIdx.x*blockDim.x + threadIdx.x;
    if (i >= (size_t)GN*FIN/8) return;
    const float4* xs = (const float4*)x;
    float4 f0 = xs[2*i], f1 = xs[2*i+1];
    __half2 h0 = __floats2half2_rn(f0.x, f0.y);
    __half2 h1 = __floats2half2_rn(f0.z, f0.w);
    __half2 h2 = __floats2half2_rn(f1.x, f1.y);
    __half2 h3 = __floats2half2_rn(f1.z, f1.w);
    uint4 o = make_uint4(*(unsigned*)&h0, *(unsigned*)&h1, *(unsigned*)&h2, *(unsigned*)&h3);
    ((uint4*)g_xh)[i] = o;
}
// merged: W conversions + pooled zero + bucket bounds
__global__ void k_misc(const float* __restrict__ W1, const float* __restrict__ W2,
                       const int* __restrict__ batch) {
    int i = blockIdx.x*blockDim.x + threadIdx.x;
    if (i < FIN*HH) g_w1h[i] = __float2half_rn(W1[i]);
    if (i < HH*HH)  g_w2h[i] = __float2half_rn(W2[i]);
    if (i < GG*HH)  g_pooled[i] = 0.f;
    if (i < GG*BB) {
        int g = i >> 5, b = i & 31;
        const int* bt = batch + (size_t)g*NN;
        int lo = 0, hi = NN;
        while (lo < hi) {
            int mid = (lo + hi) >> 1;
            if (bt[mid] < b) lo = mid + 1; else hi = mid;
        }
        g_bstart[g*(BB+1) + b] = lo;
        if (b == 0) g_bstart[g*(BB+1) + BB] = NN;
    }
}

// ---------------- CSR build ------------------------------------------------------
__global__ void k_count(const int* __restrict__ ei) {
    int idx = blockIdx.x*blockDim.x + threadIdx.x;
    if (idx >= GE) return;
    int g = idx / EE, e = idx - g*EE;
    int col = ei[(size_t)g*2*EE + EE + e];
    atomicAdd(&g_degi[g*NN + col], 1);
}
__global__ void k_scan1() {
    int g = blockIdx.x / TILES, t = blockIdx.x % TILES;
    int tid = threadIdx.x, lane = tid & 31, wid = tid >> 5;
    __shared__ int wtot[32];
    int i = t*1024 + tid;
    int c = (i < NN) ? g_degi[g*NN + i] : 0;
    int v = c;
#pragma unroll
    for (int o = 1; o < 32; o <<= 1) {
        int u = __shfl_up_sync(~0u, v, o);
        if (lane >= o) v += u;
    }
    if (lane == 31) wtot[wid] = v;
    __syncthreads();
    if (wid == 0) {
        int w2 = wtot[lane];
#pragma unroll
        for (int o = 1; o < 32; o <<= 1) {
            int u = __shfl_up_sync(~0u, w2, o);
            if (lane >= o) w2 += u;
        }
        wtot[lane] = w2;
    }
    __syncthreads();
    int excl = (wid > 0 ? wtot[wid-1] : 0) + v - c;
    if (i < NN) {
        g_off[g*(NN+1) + i] = excl;
        g_dinv[g*NN + i] = rsqrtf((float)(c + 1));
    }
    if (tid == 0) g_tsum[blockIdx.x] = wtot[31];
}
// scan2+scan3 merged: each block recomputes its tile base from g_tsum
__global__ void k_scan3m() {
    int g = blockIdx.x / TILES, t = blockIdx.x % TILES;
    int tid = threadIdx.x;
    __shared__ int part[64];
    __shared__ int sbase;
    if (tid < 64) part[tid] = (tid < t) ? g_tsum[g*TILES + tid] : 0;
    __syncthreads();
    if (tid < 32) {
        int v = part[tid] + part[tid + 32];
#pragma unroll
        for (int o = 16; o; o >>= 1) v += __shfl_xor_sync(~0u, v, o);
        if (tid == 0) sbase = v;
    }
    __syncthreads();
    int i = t*1024 + tid;
    if (i < NN) {
        int o = g_off[g*(NN+1) + i] + sbase;
        g_off[g*(NN+1) + i] = o;
        g_cur[g*NN + i] = o;
    }
    if (blockIdx.x == 0 && tid < GG)
        g_off[tid*(NN+1) + NN] = EE;
}
__global__ void k_fill(const int* __restrict__ ei) {
    int idx = blockIdx.x*blockDim.x + threadIdx.x;
    if (idx >= GE) return;
    int g = idx / EE, e = idx - g*EE;
    const int* bp = ei + (size_t)g*2*EE;
    int row = bp[e], col = bp[EE + e];
    float norm = g_dinv[g*NN + row] * g_dinv[g*NN + col];
    unsigned rec = (unsigned)row |
        ((unsigned)__half_as_ushort(__float2half_rn(norm)) << 16);
    int pos = atomicAdd(&g_cur[g*NN + col], 1);
    g_csr[(size_t)g*EE + pos] = rec;
}

// ---------------- fused gather + tensor-core matmul per layer ----------------------
// relu( (D^-1/2 A D^-1/2 + selfloop) src @ W + b ) -> fp16 hout
// 256 threads; block handles 128 nodes; warp gathers 16 rows into smem (R7 champion
// gather loop — untouched), then mma over TWO N-halves with d[8][4] accumulators to
// cut register pressure and raise occupancy (target 4 blocks/SM).
template<int K>
__global__ void __launch_bounds__(256, 4) k_fused(const __half* __restrict__ src,
        const __half* __restrict__ Wh, const float* __restrict__ bias,
        __half* __restrict__ hout) {
    constexpr int AS = K + 8;      // padded A row (halfs)
    constexpr int WS = 72;         // half-N W tile row stride (64+8 halfs, odd 16B units)
    extern __shared__ __half smh[];
    __half* As = smh;              // 128 * AS
    __half* Ws = smh + 128*AS;     // K * WS (one N-half at a time)
    int tid = threadIdx.x, wid = tid >> 5, lane = tid & 31;
    int base = blockIdx.x * 128;

    // gather phase: warp handles 16 local rows (champion inner loop)
    for (int t = 0; t < 16; t++) {
        int rl = wid*16 + t;
        int w = base + rl;
        if (w < GN) {
            int g = w / NN, n = w - g*NN;
            const __half* xg = src + (size_t)g*NN*K;
            float di = g_dinv[w], d2 = di*di;
            int s = g_off[g*(NN+1) + n], e2 = g_off[g*(NN+1) + n + 1];
            const unsigned* cs = g_csr + (size_t)g*EE;
            if (K == FIN) {
                float a0, a1;
                {
                    float2 f = __half22float2(*(const __half2*)(xg + (size_t)n*K + lane*2));
                    a0 = f.x*d2; a1 = f.y*d2;
                }
                int i = s;
                for (; i + 1 < e2; i += 2) {
                    unsigned r0 = __ldg(&cs[i]), r1 = __ldg(&cs[i+1]);
                    float n0 = rec_norm(r0), n1 = rec_norm(r1);
                    __half2 ha = *(const __half2*)(xg + (size_t)(r0 & 0xFFFFu)*K + lane*2);
                    __half2 hb = *(const __half2*)(xg + (size_t)(r1 & 0xFFFFu)*K + lane*2);
                    float2 fa = __half22float2(ha), fb = __half22float2(hb);
                    a0 = fmaf(fa.x, n0, fmaf(fb.x, n1, a0));
                    a1 = fmaf(fa.y, n0, fmaf(fb.y, n1, a1));
                }
                if (i < e2) {
                    unsigned r0 = __ldg(&cs[i]);
                    float n0 = rec_norm(r0);
                    __half2 ha = *(const __half2*)(xg + (size_t)(r0 & 0xFFFFu)*K + lane*2);
                    float2 fa = __half22float2(ha);
                    a0 = fmaf(fa.x, n0, a0);
                    a1 = fmaf(fa.y, n0, a1);
                }
                *(__half2*)(As + rl*AS + lane*2) = __floats2half2_rn(a0, a1);
            } else {
                float a0, a1, a2, a3;
                {
                    uint2 hv = *(const uint2*)(xg + (size_t)n*K + lane*4);
                    float2 f0 = __half22float2(*(__half2*)&hv.x);
                    float2 f1 = __half22float2(*(__half2*)&hv.y);
                    a0 = f0.x*d2; a1 = f0.y*d2; a2 = f1.x*d2; a3 = f1.y*d2;
                }
                int i = s;
                for (; i + 1 < e2; i += 2) {
                    unsigned r0 = __ldg(&cs[i]), r1 = __ldg(&cs[i+1]);
                    float n0 = rec_norm(r0), n1 = rec_norm(r1);
                    uint2 va = *(const uint2*)(xg + (size_t)(r0 & 0xFFFFu)*K + lane*4);
                    uint2 vb = *(const uint2*)(xg + (size_t)(r1 & 0xFFFFu)*K + lane*4);
                    float2 fa0 = __half22float2(*(__half2*)&va.x);
                    float2 fa1 = __half22float2(*(__half2*)&va.y);
                    float2 fb0 = __half22float2(*(__half2*)&vb.x);
                    float2 fb1 = __half22float2(*(__half2*)&vb.y);
                    a0 = fmaf(fa0.x, n0, fmaf(fb0.x, n1, a0));
                    a1 = fmaf(fa0.y, n0, fmaf(fb0.y, n1, a1));
                    a2 = fmaf(fa1.x, n0, fmaf(fb1.x, n1, a2));
                    a3 = fmaf(fa1.y, n0, fmaf(fb1.y, n1, a3));
                }
                if (i < e2) {
                    unsigned r0 = __ldg(&cs[i]);
                    float n0 = rec_norm(r0);
                    uint2 va = *(const uint2*)(xg + (size_t)(r0 & 0xFFFFu)*K + lane*4);
                    float2 fa0 = __half22float2(*(__half2*)&va.x);
                    float2 fa1 = __half22float2(*(__half2*)&va.y);
                    a0 = fmaf(fa0.x, n0, a0);
                    a1 = fmaf(fa0.y, n0, a1);
                    a2 = fmaf(fa1.x, n0, a2);
                    a3 = fmaf(fa1.y, n0, a3);
                }
                uint2 o;
                *(__half2*)&o.x = __floats2half2_rn(a0, a1);
                *(__half2*)&o.y = __floats2half2_rn(a2, a3);
                *(uint2*)(As + rl*AS + lane*4) = o;
            }
        } else {
            if (K == FIN) *(__half2*)(As + rl*AS + lane*2) = __floats2half2_rn(0.f, 0.f);
            else *(uint2*)(As + rl*AS + lane*4) = make_uint2(0u, 0u);
        }
    }
    __syncthreads();

    // mma phase: two N-halves, d[8][4] accumulators each
    unsigned a_sm = cvta_sm(As);
    unsigned w_sm = cvta_sm(Ws);
    int arow = wid*16 + (lane & 15);
    int asel = (lane >> 4) * 8;
    int krow = lane & 15;
    int gq = lane >> 2, tq = lane & 3;
    int row0 = base + wid*16 + gq;
    int row1 = row0 + 8;

#pragma unroll
    for (int nh = 0; nh < 2; nh++) {
        // load this half's W tile (K x 64) -> Ws
        for (int idx = tid; idx < K*8; idx += 256) {
            int r = idx >> 3, c8 = (idx & 7) << 3;
            *(uint4*)(Ws + r*WS + c8) = *(const uint4*)(Wh + r*HH + nh*64 + c8);
        }
        __syncthreads();

        float d[8][4];
#pragma unroll
        for (int t = 0; t < 8; t++) {
            d[t][0] = 0.f; d[t][1] = 0.f; d[t][2] = 0.f; d[t][3] = 0.f;
        }
        for (int kk = 0; kk < K/16; kk++) {
            unsigned a0, a1, a2, a3;
            ldmx4(a0, a1, a2, a3, a_sm + (unsigned)(arow*AS + kk*16 + asel)*2u);
#pragma unroll
            for (int nt = 0; nt < 4; nt++) {
                unsigned b0, b1, b2, b3;
                ldmx4t(b0, b1, b2, b3, w_sm + (unsigned)((kk*16 + krow)*WS + nt*16 + asel)*2u);
                mma16816(d[2*nt],   a0, a1, a2, a3, b0, b1);
                mma16816(d[2*nt+1], a0, a1, a2, a3, b2, b3);
            }
        }

        // epilogue for this half: bias + relu -> fp16
#pragma unroll
        for (int nt = 0; nt < 8; nt++) {
            int c0 = nh*64 + nt*8 + tq*2;
            float2 bc = *(const float2*)(bias + c0);
            float v00 = fmaxf(d[nt][0] + bc.x, 0.f);
            float v01 = fmaxf(d[nt][1] + bc.y, 0.f);
            float v10 = fmaxf(d[nt][2] + bc.x, 0.f);
            float v11 = fmaxf(d[nt][3] + bc.y, 0.f);
            __half2 h0 = __floats2half2_rn(v00, v01);
            __half2 h1 = __floats2half2_rn(v10, v11);
            if (row0 < GN) *(unsigned*)(hout + (size_t)row0*HH + c0) = *(unsigned*)&h0;
            if (row1 < GN) *(unsigned*)(hout + (size_t)row1*HH + c0) = *(unsigned*)&h1;
        }
        __syncthreads();   // Ws reload safety for next half
    }
}

// ---------------- pooling --------------------------------------------------------
__global__ void __launch_bounds__(256) k_pool2() {
    int g = blockIdx.x / BB, b = blockIdx.x % BB;
    int s = g_bstart[g*(BB+1) + b], e = g_bstart[g*(BB+1) + b + 1];
    int cnt = e - s;
    int tid = threadIdx.x;
    int cg = tid & 31, r0 = tid >> 5;
    float4 acc = make_float4(0.f, 0.f, 0.f, 0.f);
    const uint2* a2 = (const uint2*)(g_a2h + (size_t)g*NN*HH);
    for (int n = s + r0; n < e; n += 8) {
        uint2 v = a2[(size_t)n*32 + cg];
        __half2 h0 = *(__half2*)&v.x, h1 = *(__half2*)&v.y;
        float2 f0 = __half22float2(h0), f1 = __half22float2(h1);
        acc.x += f0.x; acc.y += f0.y; acc.z += f1.x; acc.w += f1.y;
    }
    __shared__ float4 sacc[256];
    sacc[tid] = acc;
    __syncthreads();
    if (tid < 32) {
        float4 t = sacc[tid];
#pragma unroll
        for (int r = 1; r < 8; r++) {
            float4 o = sacc[tid + 32*r];
            t.x += o.x; t.y += o.y; t.z += o.z; t.w += o.w;
        }
        float inv = (cnt > 0) ? 1.0f/(float)cnt : 0.0f;
        *(float4*)(g_emb + (size_t)blockIdx.x*HH + tid*4) =
            make_float4(t.x*inv, t.y*inv, t.z*inv, t.w*inv);
    }
}

// ---------------- fused attention (one block per batch-bucket b) -------------------
__global__ void __launch_bounds__(384) k_attall(const float* __restrict__ ipw,
        const float* __restrict__ ipb, const float* __restrict__ opw,
        const float* __restrict__ opb) {
    __shared__ float emb[GG][HH];
    __shared__ float qkv[3][GG][HH];
    __shared__ float sc[NHEADS][GG][GG];
    __shared__ float att[GG][HH];
    int b = blockIdx.x, tid = threadIdx.x;
    for (int i = tid; i < GG*HH; i += 384) {
        int g = i >> 7, c = i & 127;
        emb[g][c] = g_emb[(g*BB + b)*HH + c];
    }
    __syncthreads();
#pragma unroll
    for (int t = 0; t < 4; t++) {
        int o = tid + t*384;
        int sec = o / 512, rem = o - sec*512, g = rem >> 7, i = rem & 127;
        const float* wrow = ipw + (size_t)(sec*HH + i)*HH;
        float s = ipb[sec*HH + i];
#pragma unroll 8
        for (int j = 0; j < HH; j++) s += emb[g][j]*wrow[j];
        qkv[sec][g][i] = s;
    }
    __syncthreads();
    if (tid < 128) {
        int h = tid >> 4, g = (tid >> 2) & 3, k = tid & 3;
        float s = 0.f;
#pragma unroll
        for (int dd = 0; dd < HD; dd++) s += qkv[0][g][h*HD + dd]*qkv[1][k][h*HD + dd];
        sc[h][g][k] = s*0.25f;
    }
    __syncthreads();
    for (int o = tid; o < GG*HH; o += 384) {
        int g = o >> 7, i = o & 127, h = i >> 4;
        float s0 = sc[h][g][0], s1 = sc[h][g][1], s2 = sc[h][g][2], s3 = sc[h][g][3];
        float m = fmaxf(fmaxf(s0, s1), fmaxf(s2, s3));
        float e0 = expf(s0 - m), e1 = expf(s1 - m), e2 = expf(s2 - m), e3 = expf(s3 - m);
        float inv = 1.f/(e0 + e1 + e2 + e3);
        att[g][i] = (e0*qkv[2][0][i] + e1*qkv[2][1][i] + e2*qkv[2][2][i] + e3*qkv[2][3][i])*inv;
    }
    __syncthreads();
    for (int o = tid; o < GG*HH; o += 384) {
        int g = o >> 7, i = o & 127;
        const float* wrow = opw + (size_t)i*HH;
        float s = opb[i];
#pragma unroll 8
        for (int j = 0; j < HH; j++) s += att[g][j]*wrow[j];
        atomicAdd(&g_pooled[g*HH + i], s*(1.0f/BB));
    }
}

// ---------------- final linear ------------------------------------------------------
__global__ void k_final(const float* __restrict__ lw, const float* __restrict__ lb,
                        float* __restrict__ out) {
    __shared__ float ps[GG*HH];
    int tid = threadIdx.x;
    for (int i = tid; i < GG*HH; i += 256) ps[i] = g_pooled[i];
    __syncthreads();
    int n = blockIdx.x*8 + (tid >> 5);
    if (n >= NNODES) return;
    int lane = tid & 31;
    float4 lv = *(const float4*)(lw + (size_t)n*HH + lane*4);
    float d[GG];
#pragma unroll
    for (int g = 0; g < GG; g++) {
        const float* pg = ps + g*HH + lane*4;
        d[g] = lv.x*pg[0] + lv.y*pg[1] + lv.z*pg[2] + lv.w*pg[3];
    }
#pragma unroll
    for (int g = 0; g < GG; g++)
        for (int off = 16; off; off >>= 1)
            d[g] += __shfl_xor_sync(~0u, d[g], off);
    if (lane == 0) {
        float bn = lb[n];
#pragma unroll
        for (int g = 0; g < GG; g++)
            out[(size_t)g*NNODES + n] = (d[g] + bn)*60.0f + 50.0f;
    }
}

// ---------------- launch -------------------------------------------------------------
extern "C" void kernel_launch(void* const* d_in, const int* in_sizes, int n_in,
                              void* d_out, int out_size) {
    const float* x   = (const float*)d_in[0];
    const int*   ei  = (const int*)  d_in[1];
    const int*   bat = (const int*)  d_in[2];
    const float* W1  = (const float*)d_in[3];
    const float* b1  = (const float*)d_in[4];
    const float* W2  = (const float*)d_in[5];
    const float* b2  = (const float*)d_in[6];
    const float* ipw = (const float*)d_in[7];
    const float* ipb = (const float*)d_in[8];
    const float* opw = (const float*)d_in[9];
    const float* opb = (const float*)d_in[10];
    const float* lw  = (const float*)d_in[11];
    const float* lb  = (const float*)d_in[12];
    float* out = (float*)d_out;

    __half *p_xh, *p_a1h, *p_a2h, *p_w1h, *p_w2h;
    int *p_degi;
    cudaGetSymbolAddress((void**)&p_xh,   g_xh);
    cudaGetSymbolAddress((void**)&p_a1h,  g_a1h);
    cudaGetSymbolAddress((void**)&p_a2h,  g_a2h);
    cudaGetSymbolAddress((void**)&p_w1h,  g_w1h);
    cudaGetSymbolAddress((void**)&p_w2h,  g_w2h);
    cudaGetSymbolAddress((void**)&p_degi, g_degi);

    const int smem1 = (128*(FIN+8) + FIN*72)*2;   // 27648 B
    const int smem2 = (128*(HH+8) + HH*72)*2;     // 53248 B
    cudaFuncSetAttribute(k_fused<FIN>, cudaFuncAttributeMaxDynamicSharedMemorySize, smem1);
    cudaFuncSetAttribute(k_fused<HH>,  cudaFuncAttributeMaxDynamicSharedMemorySize, smem2);

    // independent conversions + misc first
    cudaMemsetAsync(p_degi, 0, GN*sizeof(int), 0);
    k_xcvt<<<(GN*FIN/8 + 255)/256, 256>>>(x);
    k_misc<<<(HH*HH + 255)/256, 256>>>(W1, W2, bat);

    // CSR build
    k_count<<<(GE+255)/256, 256>>>(ei);
    k_scan1<<<GG*TILES, 1024>>>();
    k_scan3m<<<GG*TILES, 1024>>>();
    k_fill<<<(GE+255)/256, 256>>>(ei);

    // layer 1 fused: gather x + matmul + relu -> a1 (fp16)
    k_fused<FIN><<<(GN+127)/128, 256, smem1>>>(p_xh, p_w1h, b1, p_a1h);
    // layer 2 fused: gather a1 + matmul + relu -> a2 (fp16)
    k_fused<HH><<<(GN+127)/128, 256, smem2>>>(p_a1h, p_w2h, b2, p_a2h);

    // mean pooling per (graph, bucket)
    k_pool2<<<GG*BB, 256>>>();

    // fused attention + projections + mean over B
    k_attall<<<BB, 384>>>(ipw, ipb, opw, opb);

    // final linear + affine
    k_final<<<(NNODES+7)/8, 256>>>(lw, lb, out);
}

// round 13
// speedup vs baseline: 1.1548x; 1.0004x over previous
#include <cuda_runtime.h>
#include <cuda_fp16.h>
#include <stdint.h>
#include <math.h>

#define GG 4
#define NN 50000
#define EE 800000
#define BB 32
#define FIN 64
#define HH 128
#define NHEADS 8
#define HD 16
#define GN (GG*NN)
#define GE (GG*EE)
#define GBH (GG*BB*HH)
#define NNODES 50000
#define TILES 49   // ceil(NN/1024)

// ---------------- scratch (device globals; no allocation allowed) -------------
__device__ __half g_xh[(size_t)GN*FIN];     // fp16 copy of x
__device__ __half g_a1h[(size_t)GN*HH];     // relu(layer1) fp16
__device__ __half g_a2h[(size_t)GN*HH];     // relu(layer2) fp16
__device__ __half g_w1h[FIN*HH];
__device__ __half g_w2h[HH*HH];
__device__ int   g_degi[GN];
__device__ float g_dinv[GN];
__device__ int   g_off[GG*(NN+1)];
__device__ int   g_cur[GN];
__device__ int   g_tsum[GG*TILES];
__device__ unsigned g_csr[(size_t)GE];      // packed {norm-fp16:hi16, row-u16:lo16}
__device__ int   g_bstart[GG*(BB+1)];
__device__ float g_emb[GBH];                // pooled means
__device__ float g_pooled[GG*HH];

// ---------------- mma / ldmatrix helpers ------------------------------------------
__device__ __forceinline__ unsigned cvta_sm(const void* p) {
    return (unsigned)__cvta_generic_to_shared(p);
}
__device__ __forceinline__ void ldmx4(unsigned& r0, unsigned& r1, unsigned& r2, unsigned& r3, unsigned a) {
    asm volatile("ldmatrix.sync.aligned.m8n8.x4.shared.b16 {%0,%1,%2,%3},[%4];"
        : "=r"(r0), "=r"(r1), "=r"(r2), "=r"(r3) : "r"(a));
}
__device__ __forceinline__ void ldmx4t(unsigned& r0, unsigned& r1, unsigned& r2, unsigned& r3, unsigned a) {
    asm volatile("ldmatrix.sync.aligned.m8n8.x4.trans.shared.b16 {%0,%1,%2,%3},[%4];"
        : "=r"(r0), "=r"(r1), "=r"(r2), "=r"(r3) : "r"(a));
}
__device__ __forceinline__ void mma16816(float* d, unsigned a0, unsigned a1, unsigned a2, unsigned a3,
                                         unsigned b0, unsigned b1) {
    asm volatile("mma.sync.aligned.m16n8k16.row.col.f32.f16.f16.f32 "
        "{%0,%1,%2,%3},{%4,%5,%6,%7},{%8,%9},{%0,%1,%2,%3};"
        : "+f"(d[0]), "+f"(d[1]), "+f"(d[2]), "+f"(d[3])
        : "r"(a0), "r"(a1), "r"(a2), "r"(a3), "r"(b0), "r"(b1));
}
__device__ __forceinline__ float rec_norm(unsigned r) {
    return __half2float(__ushort_as_half((unsigned short)(r >> 16)));
}

// ---------------- conversions ------------------------------------------------------
__global__ void k_xcvt(const float* __restrict__ x) {
    size_t i = (size_t)blockIdx.x*blockDim.x + threadIdx.x;
    if (i >= (size_t)GN*FIN/8) return;
    const float4* xs = (const float4*)x;
    float4 f0 = xs[2*i], f1 = xs[2*i+1];
    __half2 h0 = __floats2half2_rn(f0.x, f0.y);
    __half2 h1 = __floats2half2_rn(f0.z, f0.w);
    __half2 h2 = __floats2half2_rn(f1.x, f1.y);
    __half2 h3 = __floats2half2_rn(f1.z, f1.w);
    uint4 o = make_uint4(*(unsigned*)&h0, *(unsigned*)&h1, *(unsigned*)&h2, *(unsigned*)&h3);
    ((uint4*)g_xh)[i] = o;
}
// merged: W conversions + pooled zero + bucket bounds
__global__ void k_misc(const float* __restrict__ W1, const float* __restrict__ W2,
                       const int* __restrict__ batch) {
    int i = blockIdx.x*blockDim.x + threadIdx.x;
    if (i < FIN*HH) g_w1h[i] = __float2half_rn(W1[i]);
    if (i < HH*HH)  g_w2h[i] = __float2half_rn(W2[i]);
    if (i < GG*HH)  g_pooled[i] = 0.f;
    if (i < GG*BB) {
        int g = i >> 5, b = i & 31;
        const int* bt = batch + (size_t)g*NN;
        int lo = 0, hi = NN;
        while (lo < hi) {
            int mid = (lo + hi) >> 1;
            if (bt[mid] < b) lo = mid + 1; else hi = mid;
        }
        g_bstart[g*(BB+1) + b] = lo;
        if (b == 0) g_bstart[g*(BB+1) + BB] = NN;
    }
}

// ---------------- CSR build ------------------------------------------------------
__global__ void k_count(const int* __restrict__ ei) {
    int idx = blockIdx.x*blockDim.x + threadIdx.x;
    if (idx >= GE) return;
    int g = idx / EE, e = idx - g*EE;
    int col = ei[(size_t)g*2*EE + EE + e];
    atomicAdd(&g_degi[g*NN + col], 1);
}
__global__ void k_scan1() {
    int g = blockIdx.x / TILES, t = blockIdx.x % TILES;
    int tid = threadIdx.x, lane = tid & 31, wid = tid >> 5;
    __shared__ int wtot[32];
    int i = t*1024 + tid;
    int c = (i < NN) ? g_degi[g*NN + i] : 0;
    int v = c;
#pragma unroll
    for (int o = 1; o < 32; o <<= 1) {
        int u = __shfl_up_sync(~0u, v, o);
        if (lane >= o) v += u;
    }
    if (lane == 31) wtot[wid] = v;
    __syncthreads();
    if (wid == 0) {
        int w2 = wtot[lane];
#pragma unroll
        for (int o = 1; o < 32; o <<= 1) {
            int u = __shfl_up_sync(~0u, w2, o);
            if (lane >= o) w2 += u;
        }
        wtot[lane] = w2;
    }
    __syncthreads();
    int excl = (wid > 0 ? wtot[wid-1] : 0) + v - c;
    if (i < NN) {
        g_off[g*(NN+1) + i] = excl;
        g_dinv[g*NN + i] = rsqrtf((float)(c + 1));
    }
    if (tid == 0) g_tsum[blockIdx.x] = wtot[31];
}
// scan2+scan3 merged: each block recomputes its tile base from g_tsum
__global__ void k_scan3m() {
    int g = blockIdx.x / TILES, t = blockIdx.x % TILES;
    int tid = threadIdx.x;
    __shared__ int part[64];
    __shared__ int sbase;
    if (tid < 64) part[tid] = (tid < t) ? g_tsum[g*TILES + tid] : 0;
    __syncthreads();
    if (tid < 32) {
        int v = part[tid] + part[tid + 32];
#pragma unroll
        for (int o = 16; o; o >>= 1) v += __shfl_xor_sync(~0u, v, o);
        if (tid == 0) sbase = v;
    }
    __syncthreads();
    int i = t*1024 + tid;
    if (i < NN) {
        int o = g_off[g*(NN+1) + i] + sbase;
        g_off[g*(NN+1) + i] = o;
        g_cur[g*NN + i] = o;
    }
    if (blockIdx.x == 0 && tid < GG)
        g_off[tid*(NN+1) + NN] = EE;
}
__global__ void k_fill(const int* __restrict__ ei) {
    int idx = blockIdx.x*blockDim.x + threadIdx.x;
    if (idx >= GE) return;
    int g = idx / EE, e = idx - g*EE;
    const int* bp = ei + (size_t)g*2*EE;
    int row = bp[e], col = bp[EE + e];
    float norm = g_dinv[g*NN + row] * g_dinv[g*NN + col];
    unsigned rec = (unsigned)row |
        ((unsigned)__half_as_ushort(__float2half_rn(norm)) << 16);
    int pos = atomicAdd(&g_cur[g*NN + col], 1);
    g_csr[(size_t)g*EE + pos] = rec;
}

// ---------------- fused gather + tensor-core matmul per layer ----------------------
// relu( (D^-1/2 A D^-1/2 + selfloop) src @ W + b ) -> fp16 hout
// 256 threads; block handles 128 nodes; warp gathers 16 rows into smem (R7 champion
// gather loop — untouched), then mma over FOUR N-quarters with d[4][4] accumulators
// to reach 5 blocks/SM (smem 45.1KB, regs capped at 51 via launch_bounds).
template<int K>
__global__ void __launch_bounds__(256, 5) k_fused(const __half* __restrict__ src,
        const __half* __restrict__ Wh, const float* __restrict__ bias,
        __half* __restrict__ hout) {
    constexpr int AS = K + 8;      // padded A row (halfs)
    constexpr int WS = 40;         // quarter-N W tile row stride (32+8 halfs, odd 16B units)
    extern __shared__ __half smh[];
    __half* As = smh;              // 128 * AS
    __half* Ws = smh + 128*AS;     // K * WS (one N-quarter at a time)
    int tid = threadIdx.x, wid = tid >> 5, lane = tid & 31;
    int base = blockIdx.x * 128;

    // gather phase: warp handles 16 local rows (champion inner loop)
    for (int t = 0; t < 16; t++) {
        int rl = wid*16 + t;
        int w = base + rl;
        if (w < GN) {
            int g = w / NN, n = w - g*NN;
            const __half* xg = src + (size_t)g*NN*K;
            float di = g_dinv[w], d2 = di*di;
            int s = g_off[g*(NN+1) + n], e2 = g_off[g*(NN+1) + n + 1];
            const unsigned* cs = g_csr + (size_t)g*EE;
            if (K == FIN) {
                float a0, a1;
                {
                    float2 f = __half22float2(*(const __half2*)(xg + (size_t)n*K + lane*2));
                    a0 = f.x*d2; a1 = f.y*d2;
                }
                int i = s;
                for (; i + 1 < e2; i += 2) {
                    unsigned r0 = __ldg(&cs[i]), r1 = __ldg(&cs[i+1]);
                    float n0 = rec_norm(r0), n1 = rec_norm(r1);
                    __half2 ha = *(const __half2*)(xg + (size_t)(r0 & 0xFFFFu)*K + lane*2);
                    __half2 hb = *(const __half2*)(xg + (size_t)(r1 & 0xFFFFu)*K + lane*2);
                    float2 fa = __half22float2(ha), fb = __half22float2(hb);
                    a0 = fmaf(fa.x, n0, fmaf(fb.x, n1, a0));
                    a1 = fmaf(fa.y, n0, fmaf(fb.y, n1, a1));
                }
                if (i < e2) {
                    unsigned r0 = __ldg(&cs[i]);
                    float n0 = rec_norm(r0);
                    __half2 ha = *(const __half2*)(xg + (size_t)(r0 & 0xFFFFu)*K + lane*2);
                    float2 fa = __half22float2(ha);
                    a0 = fmaf(fa.x, n0, a0);
                    a1 = fmaf(fa.y, n0, a1);
                }
                *(__half2*)(As + rl*AS + lane*2) = __floats2half2_rn(a0, a1);
            } else {
                float a0, a1, a2, a3;
                {
                    uint2 hv = *(const uint2*)(xg + (size_t)n*K + lane*4);
                    float2 f0 = __half22float2(*(__half2*)&hv.x);
                    float2 f1 = __half22float2(*(__half2*)&hv.y);
                    a0 = f0.x*d2; a1 = f0.y*d2; a2 = f1.x*d2; a3 = f1.y*d2;
                }
                int i = s;
                for (; i + 1 < e2; i += 2) {
                    unsigned r0 = __ldg(&cs[i]), r1 = __ldg(&cs[i+1]);
                    float n0 = rec_norm(r0), n1 = rec_norm(r1);
                    uint2 va = *(const uint2*)(xg + (size_t)(r0 & 0xFFFFu)*K + lane*4);
                    uint2 vb = *(const uint2*)(xg + (size_t)(r1 & 0xFFFFu)*K + lane*4);
                    float2 fa0 = __half22float2(*(__half2*)&va.x);
                    float2 fa1 = __half22float2(*(__half2*)&va.y);
                    float2 fb0 = __half22float2(*(__half2*)&vb.x);
                    float2 fb1 = __half22float2(*(__half2*)&vb.y);
                    a0 = fmaf(fa0.x, n0, fmaf(fb0.x, n1, a0));
                    a1 = fmaf(fa0.y, n0, fmaf(fb0.y, n1, a1));
                    a2 = fmaf(fa1.x, n0, fmaf(fb1.x, n1, a2));
                    a3 = fmaf(fa1.y, n0, fmaf(fb1.y, n1, a3));
                }
                if (i < e2) {
                    unsigned r0 = __ldg(&cs[i]);
                    float n0 = rec_norm(r0);
                    uint2 va = *(const uint2*)(xg + (size_t)(r0 & 0xFFFFu)*K + lane*4);
                    float2 fa0 = __half22float2(*(__half2*)&va.x);
                    float2 fa1 = __half22float2(*(__half2*)&va.y);
                    a0 = fmaf(fa0.x, n0, a0);
                    a1 = fmaf(fa0.y, n0, a1);
                    a2 = fmaf(fa1.x, n0, a2);
                    a3 = fmaf(fa1.y, n0, a3);
                }
                uint2 o;
                *(__half2*)&o.x = __floats2half2_rn(a0, a1);
                *(__half2*)&o.y = __floats2half2_rn(a2, a3);
                *(uint2*)(As + rl*AS + lane*4) = o;
            }
        } else {
            if (K == FIN) *(__half2*)(As + rl*AS + lane*2) = __floats2half2_rn(0.f, 0.f);
            else *(uint2*)(As + rl*AS + lane*4) = make_uint2(0u, 0u);
        }
    }
    __syncthreads();

    // mma phase: four N-quarters, d[4][4] accumulators each
    unsigned a_sm = cvta_sm(As);
    unsigned w_sm = cvta_sm(Ws);
    int arow = wid*16 + (lane & 15);
    int asel = (lane >> 4) * 8;
    int krow = lane & 15;
    int gq = lane >> 2, tq = lane & 3;
    int row0 = base + wid*16 + gq;
    int row1 = row0 + 8;

#pragma unroll
    for (int nh = 0; nh < 4; nh++) {
        // load this quarter's W tile (K x 32) -> Ws
        for (int idx = tid; idx < K*4; idx += 256) {
            int r = idx >> 2, c8 = (idx & 3) << 3;
            *(uint4*)(Ws + r*WS + c8) = *(const uint4*)(Wh + r*HH + nh*32 + c8);
        }
        __syncthreads();

        float d[4][4];
#pragma unroll
        for (int t = 0; t < 4; t++) {
            d[t][0] = 0.f; d[t][1] = 0.f; d[t][2] = 0.f; d[t][3] = 0.f;
        }
        for (int kk = 0; kk < K/16; kk++) {
            unsigned a0, a1, a2, a3;
            ldmx4(a0, a1, a2, a3, a_sm + (unsigned)(arow*AS + kk*16 + asel)*2u);
#pragma unroll
            for (int nt = 0; nt < 2; nt++) {
                unsigned b0, b1, b2, b3;
                ldmx4t(b0, b1, b2, b3, w_sm + (unsigned)((kk*16 + krow)*WS + nt*16 + asel)*2u);
                mma16816(d[2*nt],   a0, a1, a2, a3, b0, b1);
                mma16816(d[2*nt+1], a0, a1, a2, a3, b2, b3);
            }
        }

        // epilogue for this quarter: bias + relu -> fp16
#pragma unroll
        for (int nt = 0; nt < 4; nt++) {
            int c0 = nh*32 + nt*8 + tq*2;
            float2 bc = *(const float2*)(bias + c0);
            float v00 = fmaxf(d[nt][0] + bc.x, 0.f);
            float v01 = fmaxf(d[nt][1] + bc.y, 0.f);
            float v10 = fmaxf(d[nt][2] + bc.x, 0.f);
            float v11 = fmaxf(d[nt][3] + bc.y, 0.f);
            __half2 h0 = __floats2half2_rn(v00, v01);
            __half2 h1 = __floats2half2_rn(v10, v11);
            if (row0 < GN) *(unsigned*)(hout + (size_t)row0*HH + c0) = *(unsigned*)&h0;
            if (row1 < GN) *(unsigned*)(hout + (size_t)row1*HH + c0) = *(unsigned*)&h1;
        }
        __syncthreads();   // Ws reload safety for next quarter
    }
}

// ---------------- pooling --------------------------------------------------------
__global__ void __launch_bounds__(256) k_pool2() {
    int g = blockIdx.x / BB, b = blockIdx.x % BB;
    int s = g_bstart[g*(BB+1) + b], e = g_bstart[g*(BB+1) + b + 1];
    int cnt = e - s;
    int tid = threadIdx.x;
    int cg = tid & 31, r0 = tid >> 5;
    float4 acc = make_float4(0.f, 0.f, 0.f, 0.f);
    const uint2* a2 = (const uint2*)(g_a2h + (size_t)g*NN*HH);
    for (int n = s + r0; n < e; n += 8) {
        uint2 v = a2[(size_t)n*32 + cg];
        __half2 h0 = *(__half2*)&v.x, h1 = *(__half2*)&v.y;
        float2 f0 = __half22float2(h0), f1 = __half22float2(h1);
        acc.x += f0.x; acc.y += f0.y; acc.z += f1.x; acc.w += f1.y;
    }
    __shared__ float4 sacc[256];
    sacc[tid] = acc;
    __syncthreads();
    if (tid < 32) {
        float4 t = sacc[tid];
#pragma unroll
        for (int r = 1; r < 8; r++) {
            float4 o = sacc[tid + 32*r];
            t.x += o.x; t.y += o.y; t.z += o.z; t.w += o.w;
        }
        float inv = (cnt > 0) ? 1.0f/(float)cnt : 0.0f;
        *(float4*)(g_emb + (size_t)blockIdx.x*HH + tid*4) =
            make_float4(t.x*inv, t.y*inv, t.z*inv, t.w*inv);
    }
}

// ---------------- fused attention (one block per batch-bucket b) -------------------
__global__ void __launch_bounds__(384) k_attall(const float* __restrict__ ipw,
        const float* __restrict__ ipb, const float* __restrict__ opw,
        const float* __restrict__ opb) {
    __shared__ float emb[GG][HH];
    __shared__ float qkv[3][GG][HH];
    __shared__ float sc[NHEADS][GG][GG];
    __shared__ float att[GG][HH];
    int b = blockIdx.x, tid = threadIdx.x;
    for (int i = tid; i < GG*HH; i += 384) {
        int g = i >> 7, c = i & 127;
        emb[g][c] = g_emb[(g*BB + b)*HH + c];
    }
    __syncthreads();
#pragma unroll
    for (int t = 0; t < 4; t++) {
        int o = tid + t*384;
        int sec = o / 512, rem = o - sec*512, g = rem >> 7, i = rem & 127;
        const float* wrow = ipw + (size_t)(sec*HH + i)*HH;
        float s = ipb[sec*HH + i];
#pragma unroll 8
        for (int j = 0; j < HH; j++) s += emb[g][j]*wrow[j];
        qkv[sec][g][i] = s;
    }
    __syncthreads();
    if (tid < 128) {
        int h = tid >> 4, g = (tid >> 2) & 3, k = tid & 3;
        float s = 0.f;
#pragma unroll
        for (int dd = 0; dd < HD; dd++) s += qkv[0][g][h*HD + dd]*qkv[1][k][h*HD + dd];
        sc[h][g][k] = s*0.25f;
    }
    __syncthreads();
    for (int o = tid; o < GG*HH; o += 384) {
        int g = o >> 7, i = o & 127, h = i >> 4;
        float s0 = sc[h][g][0], s1 = sc[h][g][1], s2 = sc[h][g][2], s3 = sc[h][g][3];
        float m = fmaxf(fmaxf(s0, s1), fmaxf(s2, s3));
        float e0 = expf(s0 - m), e1 = expf(s1 - m), e2 = expf(s2 - m), e3 = expf(s3 - m);
        float inv = 1.f/(e0 + e1 + e2 + e3);
        att[g][i] = (e0*qkv[2][0][i] + e1*qkv[2][1][i] + e2*qkv[2][2][i] + e3*qkv[2][3][i])*inv;
    }
    __syncthreads();
    for (int o = tid; o < GG*HH; o += 384) {
        int g = o >> 7, i = o & 127;
        const float* wrow = opw + (size_t)i*HH;
        float s = opb[i];
#pragma unroll 8
        for (int j = 0; j < HH; j++) s += att[g][j]*wrow[j];
        atomicAdd(&g_pooled[g*HH + i], s*(1.0f/BB));
    }
}

// ---------------- final linear ------------------------------------------------------
__global__ void k_final(const float* __restrict__ lw, const float* __restrict__ lb,
                        float* __restrict__ out) {
    __shared__ float ps[GG*HH];
    int tid = threadIdx.x;
    for (int i = tid; i < GG*HH; i += 256) ps[i] = g_pooled[i];
    __syncthreads();
    int n = blockIdx.x*8 + (tid >> 5);
    if (n >= NNODES) return;
    int lane = tid & 31;
    float4 lv = *(const float4*)(lw + (size_t)n*HH + lane*4);
    float d[GG];
#pragma unroll
    for (int g = 0; g < GG; g++) {
        const float* pg = ps + g*HH + lane*4;
        d[g] = lv.x*pg[0] + lv.y*pg[1] + lv.z*pg[2] + lv.w*pg[3];
    }
#pragma unroll
    for (int g = 0; g < GG; g++)
        for (int off = 16; off; off >>= 1)
            d[g] += __shfl_xor_sync(~0u, d[g], off);
    if (lane == 0) {
        float bn = lb[n];
#pragma unroll
        for (int g = 0; g < GG; g++)
            out[(size_t)g*NNODES + n] = (d[g] + bn)*60.0f + 50.0f;
    }
}

// ---------------- launch -------------------------------------------------------------
extern "C" void kernel_launch(void* const* d_in, const int* in_sizes, int n_in,
                              void* d_out, int out_size) {
    const float* x   = (const float*)d_in[0];
    const int*   ei  = (const int*)  d_in[1];
    const int*   bat = (const int*)  d_in[2];
    const float* W1  = (const float*)d_in[3];
    const float* b1  = (const float*)d_in[4];
    const float* W2  = (const float*)d_in[5];
    const float* b2  = (const float*)d_in[6];
    const float* ipw = (const float*)d_in[7];
    const float* ipb = (const float*)d_in[8];
    const float* opw = (const float*)d_in[9];
    const float* opb = (const float*)d_in[10];
    const float* lw  = (const float*)d_in[11];
    const float* lb  = (const float*)d_in[12];
    float* out = (float*)d_out;

    __half *p_xh, *p_a1h, *p_a2h, *p_w1h, *p_w2h;
    int *p_degi;
    cudaGetSymbolAddress((void**)&p_xh,   g_xh);
    cudaGetSymbolAddress((void**)&p_a1h,  g_a1h);
    cudaGetSymbolAddress((void**)&p_a2h,  g_a2h);
    cudaGetSymbolAddress((void**)&p_w1h,  g_w1h);
    cudaGetSymbolAddress((void**)&p_w2h,  g_w2h);
    cudaGetSymbolAddress((void**)&p_degi, g_degi);

    const int smem1 = (128*(FIN+8) + FIN*40)*2;   // 23552 B
    const int smem2 = (128*(HH+8) + HH*40)*2;     // 45056 B
    cudaFuncSetAttribute(k_fused<FIN>, cudaFuncAttributeMaxDynamicSharedMemorySize, smem1);
    cudaFuncSetAttribute(k_fused<HH>,  cudaFuncAttributeMaxDynamicSharedMemorySize, smem2);

    // independent conversions + misc first
    cudaMemsetAsync(p_degi, 0, GN*sizeof(int), 0);
    k_xcvt<<<(GN*FIN/8 + 255)/256, 256>>>(x);
    k_misc<<<(HH*HH + 255)/256, 256>>>(W1, W2, bat);

    // CSR build
    k_count<<<(GE+255)/256, 256>>>(ei);
    k_scan1<<<GG*TILES, 1024>>>();
    k_scan3m<<<GG*TILES, 1024>>>();
    k_fill<<<(GE+255)/256, 256>>>(ei);

    // layer 1 fused: gather x + matmul + relu -> a1 (fp16)
    k_fused<FIN><<<(GN+127)/128, 256, smem1>>>(p_xh, p_w1h, b1, p_a1h);
    // layer 2 fused: gather a1 + matmul + relu -> a2 (fp16)
    k_fused<HH><<<(GN+127)/128, 256, smem2>>>(p_a1h, p_w2h, b2, p_a2h);

    // mean pooling per (graph, bucket)
    k_pool2<<<GG*BB, 256>>>();

    // fused attention + projections + mean over B
    k_attall<<<BB, 384>>>(ipw, ipb, opw, opb);

    // final linear + affine
    k_final<<<(NNODES+7)/8, 256>>>(lw, lb, out);
}

// round 14
// speedup vs baseline: 1.1827x; 1.0242x over previous
#include <cuda_runtime.h>
#include <cuda_fp16.h>
#include <stdint.h>
#include <math.h>

#define GG 4
#define NN 50000
#define EE 800000
#define BB 32
#define FIN 64
#define HH 128
#define NHEADS 8
#define HD 16
#define GN (GG*NN)
#define GE (GG*EE)
#define GBH (GG*BB*HH)
#define NNODES 50000
#define TILES 49   // ceil(NN/1024)

// ---------------- scratch (device globals; no allocation allowed) -------------
__device__ __half g_xh[(size_t)GN*FIN];     // fp16 copy of x
__device__ unsigned char g_a1q[(size_t)GN*HH]; // relu(layer1) as e4m3 fp8
__device__ __half g_a2h[(size_t)GN*HH];     // relu(layer2) fp16
__device__ __half g_w1h[FIN*HH];
__device__ __half g_w2h[HH*HH];
__device__ int   g_degi[GN];
__device__ float g_dinv[GN];
__device__ int   g_off[GG*(NN+1)];
__device__ int   g_cur[GN];
__device__ int   g_tsum[GG*TILES];
__device__ unsigned g_csr[(size_t)GE];      // packed {norm-fp16:hi16, row-u16:lo16}
__device__ int   g_bstart[GG*(BB+1)];
__device__ float g_emb[GBH];                // pooled means
__device__ float g_pooled[GG*HH];

// ---------------- mma / ldmatrix / fp8 helpers -------------------------------------
__device__ __forceinline__ unsigned cvta_sm(const void* p) {
    return (unsigned)__cvta_generic_to_shared(p);
}
__device__ __forceinline__ void ldmx4(unsigned& r0, unsigned& r1, unsigned& r2, unsigned& r3, unsigned a) {
    asm volatile("ldmatrix.sync.aligned.m8n8.x4.shared.b16 {%0,%1,%2,%3},[%4];"
        : "=r"(r0), "=r"(r1), "=r"(r2), "=r"(r3) : "r"(a));
}
__device__ __forceinline__ void ldmx4t(unsigned& r0, unsigned& r1, unsigned& r2, unsigned& r3, unsigned a) {
    asm volatile("ldmatrix.sync.aligned.m8n8.x4.trans.shared.b16 {%0,%1,%2,%3},[%4];"
        : "=r"(r0), "=r"(r1), "=r"(r2), "=r"(r3) : "r"(a));
}
__device__ __forceinline__ void mma16816(float* d, unsigned a0, unsigned a1, unsigned a2, unsigned a3,
                                         unsigned b0, unsigned b1) {
    asm volatile("mma.sync.aligned.m16n8k16.row.col.f32.f16.f16.f32 "
        "{%0,%1,%2,%3},{%4,%5,%6,%7},{%8,%9},{%0,%1,%2,%3};"
        : "+f"(d[0]), "+f"(d[1]), "+f"(d[2]), "+f"(d[3])
        : "r"(a0), "r"(a1), "r"(a2), "r"(a3), "r"(b0), "r"(b1));
}
__device__ __forceinline__ float rec_norm(unsigned r) {
    return __half2float(__ushort_as_half((unsigned short)(r >> 16)));
}
__device__ __forceinline__ float2 fp8x2_f2(unsigned short us) {
    unsigned h2;
    asm("cvt.rn.f16x2.e4m3x2 %0, %1;" : "=r"(h2) : "h"(us));
    return __half22float2(*(__half2*)&h2);
}
__device__ __forceinline__ unsigned short f2_fp8x2(float lo, float hi) {
    unsigned short us;
    asm("cvt.rn.satfinite.e4m3x2.f32 %0, %1, %2;" : "=h"(us) : "f"(hi), "f"(lo));
    return us;
}

// ---------------- conversions ------------------------------------------------------
__global__ void k_xcvt(const float* __restrict__ x) {
    size_t i = (size_t)blockIdx.x*blockDim.x + threadIdx.x;
    if (i >= (size_t)GN*FIN/8) return;
    const float4* xs = (const float4*)x;
    float4 f0 = xs[2*i], f1 = xs[2*i+1];
    __half2 h0 = __floats2half2_rn(f0.x, f0.y);
    __half2 h1 = __floats2half2_rn(f0.z, f0.w);
    __half2 h2 = __floats2half2_rn(f1.x, f1.y);
    __half2 h3 = __floats2half2_rn(f1.z, f1.w);
    uint4 o = make_uint4(*(unsigned*)&h0, *(unsigned*)&h1, *(unsigned*)&h2, *(unsigned*)&h3);
    ((uint4*)g_xh)[i] = o;
}
// merged: W conversions + pooled zero + bucket bounds
__global__ void k_misc(const float* __restrict__ W1, const float* __restrict__ W2,
                       const int* __restrict__ batch) {
    int i = blockIdx.x*blockDim.x + threadIdx.x;
    if (i < FIN*HH) g_w1h[i] = __float2half_rn(W1[i]);
    if (i < HH*HH)  g_w2h[i] = __float2half_rn(W2[i]);
    if (i < GG*HH)  g_pooled[i] = 0.f;
    if (i < GG*BB) {
        int g = i >> 5, b = i & 31;
        const int* bt = batch + (size_t)g*NN;
        int lo = 0, hi = NN;
        while (lo < hi) {
            int mid = (lo + hi) >> 1;
            if (bt[mid] < b) lo = mid + 1; else hi = mid;
        }
        g_bstart[g*(BB+1) + b] = lo;
        if (b == 0) g_bstart[g*(BB+1) + BB] = NN;
    }
}

// ---------------- CSR build ------------------------------------------------------
__global__ void k_count(const int* __restrict__ ei) {
    int idx = blockIdx.x*blockDim.x + threadIdx.x;
    if (idx >= GE) return;
    int g = idx / EE, e = idx - g*EE;
    int col = ei[(size_t)g*2*EE + EE + e];
    atomicAdd(&g_degi[g*NN + col], 1);
}
__global__ void k_scan1() {
    int g = blockIdx.x / TILES, t = blockIdx.x % TILES;
    int tid = threadIdx.x, lane = tid & 31, wid = tid >> 5;
    __shared__ int wtot[32];
    int i = t*1024 + tid;
    int c = (i < NN) ? g_degi[g*NN + i] : 0;
    int v = c;
#pragma unroll
    for (int o = 1; o < 32; o <<= 1) {
        int u = __shfl_up_sync(~0u, v, o);
        if (lane >= o) v += u;
    }
    if (lane == 31) wtot[wid] = v;
    __syncthreads();
    if (wid == 0) {
        int w2 = wtot[lane];
#pragma unroll
        for (int o = 1; o < 32; o <<= 1) {
            int u = __shfl_up_sync(~0u, w2, o);
            if (lane >= o) w2 += u;
        }
        wtot[lane] = w2;
    }
    __syncthreads();
    int excl = (wid > 0 ? wtot[wid-1] : 0) + v - c;
    if (i < NN) {
        g_off[g*(NN+1) + i] = excl;
        g_dinv[g*NN + i] = rsqrtf((float)(c + 1));
    }
    if (tid == 0) g_tsum[blockIdx.x] = wtot[31];
}
// scan2+scan3 merged: each block recomputes its tile base from g_tsum
__global__ void k_scan3m() {
    int g = blockIdx.x / TILES, t = blockIdx.x % TILES;
    int tid = threadIdx.x;
    __shared__ int part[64];
    __shared__ int sbase;
    if (tid < 64) part[tid] = (tid < t) ? g_tsum[g*TILES + tid] : 0;
    __syncthreads();
    if (tid < 32) {
        int v = part[tid] + part[tid + 32];
#pragma unroll
        for (int o = 16; o; o >>= 1) v += __shfl_xor_sync(~0u, v, o);
        if (tid == 0) sbase = v;
    }
    __syncthreads();
    int i = t*1024 + tid;
    if (i < NN) {
        int o = g_off[g*(NN+1) + i] + sbase;
        g_off[g*(NN+1) + i] = o;
        g_cur[g*NN + i] = o;
    }
    if (blockIdx.x == 0 && tid < GG)
        g_off[tid*(NN+1) + NN] = EE;
}
__global__ void k_fill(const int* __restrict__ ei) {
    int idx = blockIdx.x*blockDim.x + threadIdx.x;
    if (idx >= GE) return;
    int g = idx / EE, e = idx - g*EE;
    const int* bp = ei + (size_t)g*2*EE;
    int row = bp[e], col = bp[EE + e];
    float norm = g_dinv[g*NN + row] * g_dinv[g*NN + col];
    unsigned rec = (unsigned)row |
        ((unsigned)__half_as_ushort(__float2half_rn(norm)) << 16);
    int pos = atomicAdd(&g_cur[g*NN + col], 1);
    g_csr[(size_t)g*EE + pos] = rec;
}

// ---------------- fused gather + tensor-core matmul per layer ----------------------
// relu( (D^-1/2 A D^-1/2 + selfloop) src @ W + b )
// K==FIN: src = fp16 x rows, output -> fp8 a1 (g_a1q)
// K==HH : src = fp8 a1 rows,  output -> fp16 a2 (hout)
// 256 threads; block handles 128 nodes; champion gather-loop structure.
template<int K>
__global__ void __launch_bounds__(256, 5) k_fused(const void* __restrict__ srcv,
        const __half* __restrict__ Wh, const float* __restrict__ bias,
        __half* __restrict__ hout) {
    constexpr int AS = K + 8;      // padded A row (halfs)
    constexpr int WS = 40;         // quarter-N W tile row stride (32+8 halfs)
    extern __shared__ __half smh[];
    __half* As = smh;              // 128 * AS
    __half* Ws = smh + 128*AS;     // K * WS (one N-quarter at a time)
    int tid = threadIdx.x, wid = tid >> 5, lane = tid & 31;
    int base = blockIdx.x * 128;

    // gather phase: warp handles 16 local rows
    for (int t = 0; t < 16; t++) {
        int rl = wid*16 + t;
        int w = base + rl;
        if (w < GN) {
            int g = w / NN, n = w - g*NN;
            float di = g_dinv[w], d2 = di*di;
            int s = g_off[g*(NN+1) + n], e2 = g_off[g*(NN+1) + n + 1];
            const unsigned* cs = g_csr + (size_t)g*EE;
            if (K == FIN) {
                const __half* xg = (const __half*)srcv + (size_t)g*NN*K;
                float a0, a1;
                {
                    float2 f = __half22float2(*(const __half2*)(xg + (size_t)n*K + lane*2));
                    a0 = f.x*d2; a1 = f.y*d2;
                }
                int i = s;
                for (; i + 1 < e2; i += 2) {
                    unsigned r0 = __ldg(&cs[i]), r1 = __ldg(&cs[i+1]);
                    float n0 = rec_norm(r0), n1 = rec_norm(r1);
                    __half2 ha = *(const __half2*)(xg + (size_t)(r0 & 0xFFFFu)*K + lane*2);
                    __half2 hb = *(const __half2*)(xg + (size_t)(r1 & 0xFFFFu)*K + lane*2);
                    float2 fa = __half22float2(ha), fb = __half22float2(hb);
                    a0 = fmaf(fa.x, n0, fmaf(fb.x, n1, a0));
                    a1 = fmaf(fa.y, n0, fmaf(fb.y, n1, a1));
                }
                if (i < e2) {
                    unsigned r0 = __ldg(&cs[i]);
                    float n0 = rec_norm(r0);
                    __half2 ha = *(const __half2*)(xg + (size_t)(r0 & 0xFFFFu)*K + lane*2);
                    float2 fa = __half22float2(ha);
                    a0 = fmaf(fa.x, n0, a0);
                    a1 = fmaf(fa.y, n0, a1);
                }
                *(__half2*)(As + rl*AS + lane*2) = __floats2half2_rn(a0, a1);
            } else {
                const unsigned char* xq = (const unsigned char*)srcv + (size_t)g*NN*K;
                float a0, a1, a2, a3;
                {
                    unsigned v = *(const unsigned*)(xq + (size_t)n*K + lane*4);
                    float2 f0 = fp8x2_f2((unsigned short)(v & 0xFFFFu));
                    float2 f1 = fp8x2_f2((unsigned short)(v >> 16));
                    a0 = f0.x*d2; a1 = f0.y*d2; a2 = f1.x*d2; a3 = f1.y*d2;
                }
                int i = s;
                for (; i + 1 < e2; i += 2) {
                    unsigned r0 = __ldg(&cs[i]), r1 = __ldg(&cs[i+1]);
                    float n0 = rec_norm(r0), n1 = rec_norm(r1);
                    unsigned va = *(const unsigned*)(xq + (size_t)(r0 & 0xFFFFu)*K + lane*4);
                    unsigned vb = *(const unsigned*)(xq + (size_t)(r1 & 0xFFFFu)*K + lane*4);
                    float2 fa0 = fp8x2_f2((unsigned short)(va & 0xFFFFu));
                    float2 fa1 = fp8x2_f2((unsigned short)(va >> 16));
                    float2 fb0 = fp8x2_f2((unsigned short)(vb & 0xFFFFu));
                    float2 fb1 = fp8x2_f2((unsigned short)(vb >> 16));
                    a0 = fmaf(fa0.x, n0, fmaf(fb0.x, n1, a0));
                    a1 = fmaf(fa0.y, n0, fmaf(fb0.y, n1, a1));
                    a2 = fmaf(fa1.x, n0, fmaf(fb1.x, n1, a2));
                    a3 = fmaf(fa1.y, n0, fmaf(fb1.y, n1, a3));
                }
                if (i < e2) {
                    unsigned r0 = __ldg(&cs[i]);
                    float n0 = rec_norm(r0);
                    unsigned va = *(const unsigned*)(xq + (size_t)(r0 & 0xFFFFu)*K + lane*4);
                    float2 fa0 = fp8x2_f2((unsigned short)(va & 0xFFFFu));
                    float2 fa1 = fp8x2_f2((unsigned short)(va >> 16));
                    a0 = fmaf(fa0.x, n0, a0);
                    a1 = fmaf(fa0.y, n0, a1);
                    a2 = fmaf(fa1.x, n0, a2);
                    a3 = fmaf(fa1.y, n0, a3);
                }
                uint2 o;
                *(__half2*)&o.x = __floats2half2_rn(a0, a1);
                *(__half2*)&o.y = __floats2half2_rn(a2, a3);
                *(uint2*)(As + rl*AS + lane*4) = o;
            }
        } else {
            if (K == FIN) *(__half2*)(As + rl*AS + lane*2) = __floats2half2_rn(0.f, 0.f);
            else *(uint2*)(As + rl*AS + lane*4) = make_uint2(0u, 0u);
        }
    }
    __syncthreads();

    // mma phase: four N-quarters, d[4][4] accumulators each
    unsigned a_sm = cvta_sm(As);
    unsigned w_sm = cvta_sm(Ws);
    int arow = wid*16 + (lane & 15);
    int asel = (lane >> 4) * 8;
    int krow = lane & 15;
    int gq = lane >> 2, tq = lane & 3;
    int row0 = base + wid*16 + gq;
    int row1 = row0 + 8;

#pragma unroll
    for (int nh = 0; nh < 4; nh++) {
        for (int idx = tid; idx < K*4; idx += 256) {
            int r = idx >> 2, c8 = (idx & 3) << 3;
            *(uint4*)(Ws + r*WS + c8) = *(const uint4*)(Wh + r*HH + nh*32 + c8);
        }
        __syncthreads();

        float d[4][4];
#pragma unroll
        for (int t = 0; t < 4; t++) {
            d[t][0] = 0.f; d[t][1] = 0.f; d[t][2] = 0.f; d[t][3] = 0.f;
        }
        for (int kk = 0; kk < K/16; kk++) {
            unsigned a0, a1, a2, a3;
            ldmx4(a0, a1, a2, a3, a_sm + (unsigned)(arow*AS + kk*16 + asel)*2u);
#pragma unroll
            for (int nt = 0; nt < 2; nt++) {
                unsigned b0, b1, b2, b3;
                ldmx4t(b0, b1, b2, b3, w_sm + (unsigned)((kk*16 + krow)*WS + nt*16 + asel)*2u);
                mma16816(d[2*nt],   a0, a1, a2, a3, b0, b1);
                mma16816(d[2*nt+1], a0, a1, a2, a3, b2, b3);
            }
        }

        // epilogue for this quarter: bias + relu -> fp8 (layer1) or fp16 (layer2)
#pragma unroll
        for (int nt = 0; nt < 4; nt++) {
            int c0 = nh*32 + nt*8 + tq*2;
            float2 bc = *(const float2*)(bias + c0);
            float v00 = fmaxf(d[nt][0] + bc.x, 0.f);
            float v01 = fmaxf(d[nt][1] + bc.y, 0.f);
            float v10 = fmaxf(d[nt][2] + bc.x, 0.f);
            float v11 = fmaxf(d[nt][3] + bc.y, 0.f);
            if (K == FIN) {
                unsigned short q0 = f2_fp8x2(v00, v01);
                unsigned short q1 = f2_fp8x2(v10, v11);
                if (row0 < GN) *(unsigned short*)(g_a1q + (size_t)row0*HH + c0) = q0;
                if (row1 < GN) *(unsigned short*)(g_a1q + (size_t)row1*HH + c0) = q1;
            } else {
                __half2 h0 = __floats2half2_rn(v00, v01);
                __half2 h1 = __floats2half2_rn(v10, v11);
                if (row0 < GN) *(unsigned*)(hout + (size_t)row0*HH + c0) = *(unsigned*)&h0;
                if (row1 < GN) *(unsigned*)(hout + (size_t)row1*HH + c0) = *(unsigned*)&h1;
            }
        }
        __syncthreads();   // Ws reload safety for next quarter
    }
}

// ---------------- pooling --------------------------------------------------------
__global__ void __launch_bounds__(256) k_pool2() {
    int g = blockIdx.x / BB, b = blockIdx.x % BB;
    int s = g_bstart[g*(BB+1) + b], e = g_bstart[g*(BB+1) + b + 1];
    int cnt = e - s;
    int tid = threadIdx.x;
    int cg = tid & 31, r0 = tid >> 5;
    float4 acc = make_float4(0.f, 0.f, 0.f, 0.f);
    const uint2* a2 = (const uint2*)(g_a2h + (size_t)g*NN*HH);
    for (int n = s + r0; n < e; n += 8) {
        uint2 v = a2[(size_t)n*32 + cg];
        __half2 h0 = *(__half2*)&v.x, h1 = *(__half2*)&v.y;
        float2 f0 = __half22float2(h0), f1 = __half22float2(h1);
        acc.x += f0.x; acc.y += f0.y; acc.z += f1.x; acc.w += f1.y;
    }
    __shared__ float4 sacc[256];
    sacc[tid] = acc;
    __syncthreads();
    if (tid < 32) {
        float4 t = sacc[tid];
#pragma unroll
        for (int r = 1; r < 8; r++) {
            float4 o = sacc[tid + 32*r];
            t.x += o.x; t.y += o.y; t.z += o.z; t.w += o.w;
        }
        float inv = (cnt > 0) ? 1.0f/(float)cnt : 0.0f;
        *(float4*)(g_emb + (size_t)blockIdx.x*HH + tid*4) =
            make_float4(t.x*inv, t.y*inv, t.z*inv, t.w*inv);
    }
}

// ---------------- fused attention (one block per batch-bucket b) -------------------
__global__ void __launch_bounds__(384) k_attall(const float* __restrict__ ipw,
        const float* __restrict__ ipb, const float* __restrict__ opw,
        const float* __restrict__ opb) {
    __shared__ float emb[GG][HH];
    __shared__ float qkv[3][GG][HH];
    __shared__ float sc[NHEADS][GG][GG];
    __shared__ float att[GG][HH];
    int b = blockIdx.x, tid = threadIdx.x;
    for (int i = tid; i < GG*HH; i += 384) {
        int g = i >> 7, c = i & 127;
        emb[g][c] = g_emb[(g*BB + b)*HH + c];
    }
    __syncthreads();
#pragma unroll
    for (int t = 0; t < 4; t++) {
        int o = tid + t*384;
        int sec = o / 512, rem = o - sec*512, g = rem >> 7, i = rem & 127;
        const float* wrow = ipw + (size_t)(sec*HH + i)*HH;
        float s = ipb[sec*HH + i];
#pragma unroll 8
        for (int j = 0; j < HH; j++) s += emb[g][j]*wrow[j];
        qkv[sec][g][i] = s;
    }
    __syncthreads();
    if (tid < 128) {
        int h = tid >> 4, g = (tid >> 2) & 3, k = tid & 3;
        float s = 0.f;
#pragma unroll
        for (int dd = 0; dd < HD; dd++) s += qkv[0][g][h*HD + dd]*qkv[1][k][h*HD + dd];
        sc[h][g][k] = s*0.25f;
    }
    __syncthreads();
    for (int o = tid; o < GG*HH; o += 384) {
        int g = o >> 7, i = o & 127, h = i >> 4;
        float s0 = sc[h][g][0], s1 = sc[h][g][1], s2 = sc[h][g][2], s3 = sc[h][g][3];
        float m = fmaxf(fmaxf(s0, s1), fmaxf(s2, s3));
        float e0 = expf(s0 - m), e1 = expf(s1 - m), e2 = expf(s2 - m), e3 = expf(s3 - m);
        float inv = 1.f/(e0 + e1 + e2 + e3);
        att[g][i] = (e0*qkv[2][0][i] + e1*qkv[2][1][i] + e2*qkv[2][2][i] + e3*qkv[2][3][i])*inv;
    }
    __syncthreads();
    for (int o = tid; o < GG*HH; o += 384) {
        int g = o >> 7, i = o & 127;
        const float* wrow = opw + (size_t)i*HH;
        float s = opb[i];
#pragma unroll 8
        for (int j = 0; j < HH; j++) s += att[g][j]*wrow[j];
        atomicAdd(&g_pooled[g*HH + i], s*(1.0f/BB));
    }
}

// ---------------- final linear ------------------------------------------------------
__global__ void k_final(const float* __restrict__ lw, const float* __restrict__ lb,
                        float* __restrict__ out) {
    __shared__ float ps[GG*HH];
    int tid = threadIdx.x;
    for (int i = tid; i < GG*HH; i += 256) ps[i] = g_pooled[i];
    __syncthreads();
    int n = blockIdx.x*8 + (tid >> 5);
    if (n >= NNODES) return;
    int lane = tid & 31;
    float4 lv = *(const float4*)(lw + (size_t)n*HH + lane*4);
    float d[GG];
#pragma unroll
    for (int g = 0; g < GG; g++) {
        const float* pg = ps + g*HH + lane*4;
        d[g] = lv.x*pg[0] + lv.y*pg[1] + lv.z*pg[2] + lv.w*pg[3];
    }
#pragma unroll
    for (int g = 0; g < GG; g++)
        for (int off = 16; off; off >>= 1)
            d[g] += __shfl_xor_sync(~0u, d[g], off);
    if (lane == 0) {
        float bn = lb[n];
#pragma unroll
        for (int g = 0; g < GG; g++)
            out[(size_t)g*NNODES + n] = (d[g] + bn)*60.0f + 50.0f;
    }
}

// ---------------- launch -------------------------------------------------------------
extern "C" void kernel_launch(void* const* d_in, const int* in_sizes, int n_in,
                              void* d_out, int out_size) {
    const float* x   = (const float*)d_in[0];
    const int*   ei  = (const int*)  d_in[1];
    const int*   bat = (const int*)  d_in[2];
    const float* W1  = (const float*)d_in[3];
    const float* b1  = (const float*)d_in[4];
    const float* W2  = (const float*)d_in[5];
    const float* b2  = (const float*)d_in[6];
    const float* ipw = (const float*)d_in[7];
    const float* ipb = (const float*)d_in[8];
    const float* opw = (const float*)d_in[9];
    const float* opb = (const float*)d_in[10];
    const float* lw  = (const float*)d_in[11];
    const float* lb  = (const float*)d_in[12];
    float* out = (float*)d_out;

    __half *p_xh, *p_a2h, *p_w1h, *p_w2h;
    unsigned char *p_a1q;
    int *p_degi;
    cudaGetSymbolAddress((void**)&p_xh,   g_xh);
    cudaGetSymbolAddress((void**)&p_a1q,  g_a1q);
    cudaGetSymbolAddress((void**)&p_a2h,  g_a2h);
    cudaGetSymbolAddress((void**)&p_w1h,  g_w1h);
    cudaGetSymbolAddress((void**)&p_w2h,  g_w2h);
    cudaGetSymbolAddress((void**)&p_degi, g_degi);

    const int smem1 = (128*(FIN+8) + FIN*40)*2;   // 23552 B
    const int smem2 = (128*(HH+8) + HH*40)*2;     // 45056 B
    cudaFuncSetAttribute(k_fused<FIN>, cudaFuncAttributeMaxDynamicSharedMemorySize, smem1);
    cudaFuncSetAttribute(k_fused<HH>,  cudaFuncAttributeMaxDynamicSharedMemorySize, smem2);

    // independent conversions + misc first
    cudaMemsetAsync(p_degi, 0, GN*sizeof(int), 0);
    k_xcvt<<<(GN*FIN/8 + 255)/256, 256>>>(x);
    k_misc<<<(HH*HH + 255)/256, 256>>>(W1, W2, bat);

    // CSR build
    k_count<<<(GE+255)/256, 256>>>(ei);
    k_scan1<<<GG*TILES, 1024>>>();
    k_scan3m<<<GG*TILES, 1024>>>();
    k_fill<<<(GE+255)/256, 256>>>(ei);

    // layer 1 fused: gather fp16 x + matmul + relu -> fp8 a1
    k_fused<FIN><<<(GN+127)/128, 256, smem1>>>(p_xh, p_w1h, b1, nullptr);
    // layer 2 fused: gather fp8 a1 + matmul + relu -> fp16 a2
    k_fused<HH><<<(GN+127)/128, 256, smem2>>>(p_a1q, p_w2h, b2, p_a2h);

    // mean pooling per (graph, bucket)
    k_pool2<<<GG*BB, 256>>>();

    // fused attention + projections + mean over B
    k_attall<<<BB, 384>>>(ipw, ipb, opw, opb);

    // final linear + affine
    k_final<<<(NNODES+7)/8, 256>>>(lw, lb, out);
}

// round 15
// speedup vs baseline: 1.2002x; 1.0148x over previous
#include <cuda_runtime.h>
#include <cuda_fp16.h>
#include <stdint.h>
#include <math.h>

#define GG 4
#define NN 50000
#define EE 800000
#define BB 32
#define FIN 64
#define HH 128
#define NHEADS 8
#define HD 16
#define GN (GG*NN)
#define GE (GG*EE)
#define GBH (GG*BB*HH)
#define NNODES 50000
#define TILES 49   // ceil(NN/1024)

// ---------------- scratch (device globals; no allocation allowed) -------------
__device__ unsigned char g_xq[(size_t)GN*FIN];  // x as e4m3 fp8
__device__ unsigned char g_a1q[(size_t)GN*HH];  // relu(layer1) as e4m3 fp8
__device__ unsigned char g_a2q[(size_t)GN*HH];  // relu(layer2) as e4m3 fp8
__device__ __half g_w1h[FIN*HH];
__device__ __half g_w2h[HH*HH];
__device__ int   g_degi[GN];
__device__ float g_dinv[GN];
__device__ int   g_off[GG*(NN+1)];
__device__ int   g_cur[GN];
__device__ int   g_tsum[GG*TILES];
__device__ unsigned g_csr[(size_t)GE];      // packed {norm-fp16:hi16, row-u16:lo16}
__device__ int   g_bstart[GG*(BB+1)];
__device__ float g_emb[GBH];                // pooled means
__device__ float g_pooled[GG*HH];

// ---------------- mma / ldmatrix / fp8 helpers -------------------------------------
__device__ __forceinline__ unsigned cvta_sm(const void* p) {
    return (unsigned)__cvta_generic_to_shared(p);
}
__device__ __forceinline__ void ldmx4(unsigned& r0, unsigned& r1, unsigned& r2, unsigned& r3, unsigned a) {
    asm volatile("ldmatrix.sync.aligned.m8n8.x4.shared.b16 {%0,%1,%2,%3},[%4];"
        : "=r"(r0), "=r"(r1), "=r"(r2), "=r"(r3) : "r"(a));
}
__device__ __forceinline__ void ldmx4t(unsigned& r0, unsigned& r1, unsigned& r2, unsigned& r3, unsigned a) {
    asm volatile("ldmatrix.sync.aligned.m8n8.x4.trans.shared.b16 {%0,%1,%2,%3},[%4];"
        : "=r"(r0), "=r"(r1), "=r"(r2), "=r"(r3) : "r"(a));
}
__device__ __forceinline__ void mma16816(float* d, unsigned a0, unsigned a1, unsigned a2, unsigned a3,
                                         unsigned b0, unsigned b1) {
    asm volatile("mma.sync.aligned.m16n8k16.row.col.f32.f16.f16.f32 "
        "{%0,%1,%2,%3},{%4,%5,%6,%7},{%8,%9},{%0,%1,%2,%3};"
        : "+f"(d[0]), "+f"(d[1]), "+f"(d[2]), "+f"(d[3])
        : "r"(a0), "r"(a1), "r"(a2), "r"(a3), "r"(b0), "r"(b1));
}
__device__ __forceinline__ float rec_norm(unsigned r) {
    return __half2float(__ushort_as_half((unsigned short)(r >> 16)));
}
__device__ __forceinline__ float2 fp8x2_f2(unsigned short us) {
    unsigned h2;
    asm("cvt.rn.f16x2.e4m3x2 %0, %1;" : "=r"(h2) : "h"(us));
    return __half22float2(*(__half2*)&h2);
}
__device__ __forceinline__ unsigned short f2_fp8x2(float lo, float hi) {
    unsigned short us;
    asm("cvt.rn.satfinite.e4m3x2.f32 %0, %1, %2;" : "=h"(us) : "f"(hi), "f"(lo));
    return us;
}

// ---------------- conversions ------------------------------------------------------
// x (fp32) -> e4m3 fp8; thread handles 8 elements
__global__ void k_xcvt(const float* __restrict__ x) {
    size_t i = (size_t)blockIdx.x*blockDim.x + threadIdx.x;
    if (i >= (size_t)GN*FIN/8) return;
    const float4* xs = (const float4*)x;
    float4 f0 = xs[2*i], f1 = xs[2*i+1];
    unsigned short q0 = f2_fp8x2(f0.x, f0.y);
    unsigned short q1 = f2_fp8x2(f0.z, f0.w);
    unsigned short q2 = f2_fp8x2(f1.x, f1.y);
    unsigned short q3 = f2_fp8x2(f1.z, f1.w);
    uint2 o = make_uint2((unsigned)q0 | ((unsigned)q1 << 16),
                         (unsigned)q2 | ((unsigned)q3 << 16));
    ((uint2*)g_xq)[i] = o;
}
// merged: W conversions + pooled zero + bucket bounds
__global__ void k_misc(const float* __restrict__ W1, const float* __restrict__ W2,
                       const int* __restrict__ batch) {
    int i = blockIdx.x*blockDim.x + threadIdx.x;
    if (i < FIN*HH) g_w1h[i] = __float2half_rn(W1[i]);
    if (i < HH*HH)  g_w2h[i] = __float2half_rn(W2[i]);
    if (i < GG*HH)  g_pooled[i] = 0.f;
    if (i < GG*BB) {
        int g = i >> 5, b = i & 31;
        const int* bt = batch + (size_t)g*NN;
        int lo = 0, hi = NN;
        while (lo < hi) {
            int mid = (lo + hi) >> 1;
            if (bt[mid] < b) lo = mid + 1; else hi = mid;
        }
        g_bstart[g*(BB+1) + b] = lo;
        if (b == 0) g_bstart[g*(BB+1) + BB] = NN;
    }
}

// ---------------- CSR build ------------------------------------------------------
__global__ void k_count(const int* __restrict__ ei) {
    int idx = blockIdx.x*blockDim.x + threadIdx.x;
    if (idx >= GE) return;
    int g = idx / EE, e = idx - g*EE;
    int col = ei[(size_t)g*2*EE + EE + e];
    atomicAdd(&g_degi[g*NN + col], 1);
}
__global__ void k_scan1() {
    int g = blockIdx.x / TILES, t = blockIdx.x % TILES;
    int tid = threadIdx.x, lane = tid & 31, wid = tid >> 5;
    __shared__ int wtot[32];
    int i = t*1024 + tid;
    int c = (i < NN) ? g_degi[g*NN + i] : 0;
    int v = c;
#pragma unroll
    for (int o = 1; o < 32; o <<= 1) {
        int u = __shfl_up_sync(~0u, v, o);
        if (lane >= o) v += u;
    }
    if (lane == 31) wtot[wid] = v;
    __syncthreads();
    if (wid == 0) {
        int w2 = wtot[lane];
#pragma unroll
        for (int o = 1; o < 32; o <<= 1) {
            int u = __shfl_up_sync(~0u, w2, o);
            if (lane >= o) w2 += u;
        }
        wtot[lane] = w2;
    }
    __syncthreads();
    int excl = (wid > 0 ? wtot[wid-1] : 0) + v - c;
    if (i < NN) {
        g_off[g*(NN+1) + i] = excl;
        g_dinv[g*NN + i] = rsqrtf((float)(c + 1));
    }
    if (tid == 0) g_tsum[blockIdx.x] = wtot[31];
}
// scan2+scan3 merged: each block recomputes its tile base from g_tsum
__global__ void k_scan3m() {
    int g = blockIdx.x / TILES, t = blockIdx.x % TILES;
    int tid = threadIdx.x;
    __shared__ int part[64];
    __shared__ int sbase;
    if (tid < 64) part[tid] = (tid < t) ? g_tsum[g*TILES + tid] : 0;
    __syncthreads();
    if (tid < 32) {
        int v = part[tid] + part[tid + 32];
#pragma unroll
        for (int o = 16; o; o >>= 1) v += __shfl_xor_sync(~0u, v, o);
        if (tid == 0) sbase = v;
    }
    __syncthreads();
    int i = t*1024 + tid;
    if (i < NN) {
        int o = g_off[g*(NN+1) + i] + sbase;
        g_off[g*(NN+1) + i] = o;
        g_cur[g*NN + i] = o;
    }
    if (blockIdx.x == 0 && tid < GG)
        g_off[tid*(NN+1) + NN] = EE;
}
__global__ void k_fill(const int* __restrict__ ei) {
    int idx = blockIdx.x*blockDim.x + threadIdx.x;
    if (idx >= GE) return;
    int g = idx / EE, e = idx - g*EE;
    const int* bp = ei + (size_t)g*2*EE;
    int row = bp[e], col = bp[EE + e];
    float norm = g_dinv[g*NN + row] * g_dinv[g*NN + col];
    unsigned rec = (unsigned)row |
        ((unsigned)__half_as_ushort(__float2half_rn(norm)) << 16);
    int pos = atomicAdd(&g_cur[g*NN + col], 1);
    g_csr[(size_t)g*EE + pos] = rec;
}

// ---------------- fused gather + tensor-core matmul per layer ----------------------
// relu( (D^-1/2 A D^-1/2 + selfloop) src @ W + b ) -> fp8 qout
// src is fp8 rows (K bytes/row). 256 threads; block = 128 nodes; champion gather
// structure; mma over four N-quarters with d[4][4] accumulators.
template<int K>
__global__ void __launch_bounds__(256, 5) k_fused(const unsigned char* __restrict__ src,
        const __half* __restrict__ Wh, const float* __restrict__ bias,
        unsigned char* __restrict__ qout) {
    constexpr int AS = K + 8;      // padded A row (halfs)
    constexpr int WS = 40;         // quarter-N W tile row stride (32+8 halfs)
    extern __shared__ __half smh[];
    __half* As = smh;              // 128 * AS
    __half* Ws = smh + 128*AS;     // K * WS (one N-quarter at a time)
    int tid = threadIdx.x, wid = tid >> 5, lane = tid & 31;
    int base = blockIdx.x * 128;

    // gather phase: warp handles 16 local rows
    for (int t = 0; t < 16; t++) {
        int rl = wid*16 + t;
        int w = base + rl;
        if (w < GN) {
            int g = w / NN, n = w - g*NN;
            const unsigned char* xq = src + (size_t)g*NN*K;
            float di = g_dinv[w], d2 = di*di;
            int s = g_off[g*(NN+1) + n], e2 = g_off[g*(NN+1) + n + 1];
            const unsigned* cs = g_csr + (size_t)g*EE;
            if (K == FIN) {
                // lane covers 2 fp8 elems (2B)
                float a0, a1;
                {
                    unsigned short v = *(const unsigned short*)(xq + (size_t)n*K + lane*2);
                    float2 f = fp8x2_f2(v);
                    a0 = f.x*d2; a1 = f.y*d2;
                }
                int i = s;
                for (; i + 1 < e2; i += 2) {
                    unsigned r0 = __ldg(&cs[i]), r1 = __ldg(&cs[i+1]);
                    float n0 = rec_norm(r0), n1 = rec_norm(r1);
                    unsigned short va = *(const unsigned short*)(xq + (size_t)(r0 & 0xFFFFu)*K + lane*2);
                    unsigned short vb = *(const unsigned short*)(xq + (size_t)(r1 & 0xFFFFu)*K + lane*2);
                    float2 fa = fp8x2_f2(va), fb = fp8x2_f2(vb);
                    a0 = fmaf(fa.x, n0, fmaf(fb.x, n1, a0));
                    a1 = fmaf(fa.y, n0, fmaf(fb.y, n1, a1));
                }
                if (i < e2) {
                    unsigned r0 = __ldg(&cs[i]);
                    float n0 = rec_norm(r0);
                    unsigned short va = *(const unsigned short*)(xq + (size_t)(r0 & 0xFFFFu)*K + lane*2);
                    float2 fa = fp8x2_f2(va);
                    a0 = fmaf(fa.x, n0, a0);
                    a1 = fmaf(fa.y, n0, a1);
                }
                *(__half2*)(As + rl*AS + lane*2) = __floats2half2_rn(a0, a1);
            } else {
                // lane covers 4 fp8 elems (4B)
                float a0, a1, a2, a3;
                {
                    unsigned v = *(const unsigned*)(xq + (size_t)n*K + lane*4);
                    float2 f0 = fp8x2_f2((unsigned short)(v & 0xFFFFu));
                    float2 f1 = fp8x2_f2((unsigned short)(v >> 16));
                    a0 = f0.x*d2; a1 = f0.y*d2; a2 = f1.x*d2; a3 = f1.y*d2;
                }
                int i = s;
                for (; i + 1 < e2; i += 2) {
                    unsigned r0 = __ldg(&cs[i]), r1 = __ldg(&cs[i+1]);
                    float n0 = rec_norm(r0), n1 = rec_norm(r1);
                    unsigned va = *(const unsigned*)(xq + (size_t)(r0 & 0xFFFFu)*K + lane*4);
                    unsigned vb = *(const unsigned*)(xq + (size_t)(r1 & 0xFFFFu)*K + lane*4);
                    float2 fa0 = fp8x2_f2((unsigned short)(va & 0xFFFFu));
                    float2 fa1 = fp8x2_f2((unsigned short)(va >> 16));
                    float2 fb0 = fp8x2_f2((unsigned short)(vb & 0xFFFFu));
                    float2 fb1 = fp8x2_f2((unsigned short)(vb >> 16));
                    a0 = fmaf(fa0.x, n0, fmaf(fb0.x, n1, a0));
                    a1 = fmaf(fa0.y, n0, fmaf(fb0.y, n1, a1));
                    a2 = fmaf(fa1.x, n0, fmaf(fb1.x, n1, a2));
                    a3 = fmaf(fa1.y, n0, fmaf(fb1.y, n1, a3));
                }
                if (i < e2) {
                    unsigned r0 = __ldg(&cs[i]);
                    float n0 = rec_norm(r0);
                    unsigned va = *(const unsigned*)(xq + (size_t)(r0 & 0xFFFFu)*K + lane*4);
                    float2 fa0 = fp8x2_f2((unsigned short)(va & 0xFFFFu));
                    float2 fa1 = fp8x2_f2((unsigned short)(va >> 16));
                    a0 = fmaf(fa0.x, n0, a0);
                    a1 = fmaf(fa0.y, n0, a1);
                    a2 = fmaf(fa1.x, n0, a2);
                    a3 = fmaf(fa1.y, n0, a3);
                }
                uint2 o;
                *(__half2*)&o.x = __floats2half2_rn(a0, a1);
                *(__half2*)&o.y = __floats2half2_rn(a2, a3);
                *(uint2*)(As + rl*AS + lane*4) = o;
            }
        } else {
            if (K == FIN) *(__half2*)(As + rl*AS + lane*2) = __floats2half2_rn(0.f, 0.f);
            else *(uint2*)(As + rl*AS + lane*4) = make_uint2(0u, 0u);
        }
    }
    __syncthreads();

    // mma phase: four N-quarters, d[4][4] accumulators each
    unsigned a_sm = cvta_sm(As);
    unsigned w_sm = cvta_sm(Ws);
    int arow = wid*16 + (lane & 15);
    int asel = (lane >> 4) * 8;
    int krow = lane & 15;
    int gq = lane >> 2, tq = lane & 3;
    int row0 = base + wid*16 + gq;
    int row1 = row0 + 8;

#pragma unroll
    for (int nh = 0; nh < 4; nh++) {
        for (int idx = tid; idx < K*4; idx += 256) {
            int r = idx >> 2, c8 = (idx & 3) << 3;
            *(uint4*)(Ws + r*WS + c8) = *(const uint4*)(Wh + r*HH + nh*32 + c8);
        }
        __syncthreads();

        float d[4][4];
#pragma unroll
        for (int t = 0; t < 4; t++) {
            d[t][0] = 0.f; d[t][1] = 0.f; d[t][2] = 0.f; d[t][3] = 0.f;
        }
        for (int kk = 0; kk < K/16; kk++) {
            unsigned a0, a1, a2, a3;
            ldmx4(a0, a1, a2, a3, a_sm + (unsigned)(arow*AS + kk*16 + asel)*2u);
#pragma unroll
            for (int nt = 0; nt < 2; nt++) {
                unsigned b0, b1, b2, b3;
                ldmx4t(b0, b1, b2, b3, w_sm + (unsigned)((kk*16 + krow)*WS + nt*16 + asel)*2u);
                mma16816(d[2*nt],   a0, a1, a2, a3, b0, b1);
                mma16816(d[2*nt+1], a0, a1, a2, a3, b2, b3);
            }
        }

        // epilogue for this quarter: bias + relu -> fp8
#pragma unroll
        for (int nt = 0; nt < 4; nt++) {
            int c0 = nh*32 + nt*8 + tq*2;
            float2 bc = *(const float2*)(bias + c0);
            float v00 = fmaxf(d[nt][0] + bc.x, 0.f);
            float v01 = fmaxf(d[nt][1] + bc.y, 0.f);
            float v10 = fmaxf(d[nt][2] + bc.x, 0.f);
            float v11 = fmaxf(d[nt][3] + bc.y, 0.f);
            unsigned short q0 = f2_fp8x2(v00, v01);
            unsigned short q1 = f2_fp8x2(v10, v11);
            if (row0 < GN) *(unsigned short*)(qout + (size_t)row0*HH + c0) = q0;
            if (row1 < GN) *(unsigned short*)(qout + (size_t)row1*HH + c0) = q1;
        }
        __syncthreads();   // Ws reload safety for next quarter
    }
}

// ---------------- pooling (reads fp8 a2) --------------------------------------------
__global__ void __launch_bounds__(256) k_pool2() {
    int g = blockIdx.x / BB, b = blockIdx.x % BB;
    int s = g_bstart[g*(BB+1) + b], e = g_bstart[g*(BB+1) + b + 1];
    int cnt = e - s;
    int tid = threadIdx.x;
    int cg = tid & 31, r0 = tid >> 5;
    float4 acc = make_float4(0.f, 0.f, 0.f, 0.f);
    const unsigned* a2 = (const unsigned*)(g_a2q + (size_t)g*NN*HH);
    for (int n = s + r0; n < e; n += 8) {
        unsigned v = a2[(size_t)n*32 + cg];
        float2 f0 = fp8x2_f2((unsigned short)(v & 0xFFFFu));
        float2 f1 = fp8x2_f2((unsigned short)(v >> 16));
        acc.x += f0.x; acc.y += f0.y; acc.z += f1.x; acc.w += f1.y;
    }
    __shared__ float4 sacc[256];
    sacc[tid] = acc;
    __syncthreads();
    if (tid < 32) {
        float4 t = sacc[tid];
#pragma unroll
        for (int r = 1; r < 8; r++) {
            float4 o = sacc[tid + 32*r];
            t.x += o.x; t.y += o.y; t.z += o.z; t.w += o.w;
        }
        float inv = (cnt > 0) ? 1.0f/(float)cnt : 0.0f;
        *(float4*)(g_emb + (size_t)blockIdx.x*HH + tid*4) =
            make_float4(t.x*inv, t.y*inv, t.z*inv, t.w*inv);
    }
}

// ---------------- fused attention (one block per batch-bucket b) -------------------
__global__ void __launch_bounds__(384) k_attall(const float* __restrict__ ipw,
        const float* __restrict__ ipb, const float* __restrict__ opw,
        const float* __restrict__ opb) {
    __shared__ float emb[GG][HH];
    __shared__ float qkv[3][GG][HH];
    __shared__ float sc[NHEADS][GG][GG];
    __shared__ float att[GG][HH];
    int b = blockIdx.x, tid = threadIdx.x;
    for (int i = tid; i < GG*HH; i += 384) {
        int g = i >> 7, c = i & 127;
        emb[g][c] = g_emb[(g*BB + b)*HH + c];
    }
    __syncthreads();
#pragma unroll
    for (int t = 0; t < 4; t++) {
        int o = tid + t*384;
        int sec = o / 512, rem = o - sec*512, g = rem >> 7, i = rem & 127;
        const float* wrow = ipw + (size_t)(sec*HH + i)*HH;
        float s = ipb[sec*HH + i];
#pragma unroll 8
        for (int j = 0; j < HH; j++) s += emb[g][j]*wrow[j];
        qkv[sec][g][i] = s;
    }
    __syncthreads();
    if (tid < 128) {
        int h = tid >> 4, g = (tid >> 2) & 3, k = tid & 3;
        float s = 0.f;
#pragma unroll
        for (int dd = 0; dd < HD; dd++) s += qkv[0][g][h*HD + dd]*qkv[1][k][h*HD + dd];
        sc[h][g][k] = s*0.25f;
    }
    __syncthreads();
    for (int o = tid; o < GG*HH; o += 384) {
        int g = o >> 7, i = o & 127, h = i >> 4;
        float s0 = sc[h][g][0], s1 = sc[h][g][1], s2 = sc[h][g][2], s3 = sc[h][g][3];
        float m = fmaxf(fmaxf(s0, s1), fmaxf(s2, s3));
        float e0 = expf(s0 - m), e1 = expf(s1 - m), e2 = expf(s2 - m), e3 = expf(s3 - m);
        float inv = 1.f/(e0 + e1 + e2 + e3);
        att[g][i] = (e0*qkv[2][0][i] + e1*qkv[2][1][i] + e2*qkv[2][2][i] + e3*qkv[2][3][i])*inv;
    }
    __syncthreads();
    for (int o = tid; o < GG*HH; o += 384) {
        int g = o >> 7, i = o & 127;
        const float* wrow = opw + (size_t)i*HH;
        float s = opb[i];
#pragma unroll 8
        for (int j = 0; j < HH; j++) s += att[g][j]*wrow[j];
        atomicAdd(&g_pooled[g*HH + i], s*(1.0f/BB));
    }
}

// ---------------- final linear ------------------------------------------------------
__global__ void k_final(const float* __restrict__ lw, const float* __restrict__ lb,
                        float* __restrict__ out) {
    __shared__ float ps[GG*HH];
    int tid = threadIdx.x;
    for (int i = tid; i < GG*HH; i += 256) ps[i] = g_pooled[i];
    __syncthreads();
    int n = blockIdx.x*8 + (tid >> 5);
    if (n >= NNODES) return;
    int lane = tid & 31;
    float4 lv = *(const float4*)(lw + (size_t)n*HH + lane*4);
    float d[GG];
#pragma unroll
    for (int g = 0; g < GG; g++) {
        const float* pg = ps + g*HH + lane*4;
        d[g] = lv.x*pg[0] + lv.y*pg[1] + lv.z*pg[2] + lv.w*pg[3];
    }
#pragma unroll
    for (int g = 0; g < GG; g++)
        for (int off = 16; off; off >>= 1)
            d[g] += __shfl_xor_sync(~0u, d[g], off);
    if (lane == 0) {
        float bn = lb[n];
#pragma unroll
        for (int g = 0; g < GG; g++)
            out[(size_t)g*NNODES + n] = (d[g] + bn)*60.0f + 50.0f;
    }
}

// ---------------- launch -------------------------------------------------------------
extern "C" void kernel_launch(void* const* d_in, const int* in_sizes, int n_in,
                              void* d_out, int out_size) {
    const float* x   = (const float*)d_in[0];
    const int*   ei  = (const int*)  d_in[1];
    const int*   bat = (const int*)  d_in[2];
    const float* W1  = (const float*)d_in[3];
    const float* b1  = (const float*)d_in[4];
    const float* W2  = (const float*)d_in[5];
    const float* b2  = (const float*)d_in[6];
    const float* ipw = (const float*)d_in[7];
    const float* ipb = (const float*)d_in[8];
    const float* opw = (const float*)d_in[9];
    const float* opb = (const float*)d_in[10];
    const float* lw  = (const float*)d_in[11];
    const float* lb  = (const float*)d_in[12];
    float* out = (float*)d_out;

    __half *p_w1h, *p_w2h;
    unsigned char *p_xq, *p_a1q, *p_a2q;
    int *p_degi;
    cudaGetSymbolAddress((void**)&p_xq,   g_xq);
    cudaGetSymbolAddress((void**)&p_a1q,  g_a1q);
    cudaGetSymbolAddress((void**)&p_a2q,  g_a2q);
    cudaGetSymbolAddress((void**)&p_w1h,  g_w1h);
    cudaGetSymbolAddress((void**)&p_w2h,  g_w2h);
    cudaGetSymbolAddress((void**)&p_degi, g_degi);

    const int smem1 = (128*(FIN+8) + FIN*40)*2;   // 23552 B
    const int smem2 = (128*(HH+8) + HH*40)*2;     // 45056 B
    cudaFuncSetAttribute(k_fused<FIN>, cudaFuncAttributeMaxDynamicSharedMemorySize, smem1);
    cudaFuncSetAttribute(k_fused<HH>,  cudaFuncAttributeMaxDynamicSharedMemorySize, smem2);

    // independent conversions + misc first
    cudaMemsetAsync(p_degi, 0, GN*sizeof(int), 0);
    k_xcvt<<<(GN*FIN/8 + 255)/256, 256>>>(x);
    k_misc<<<(HH*HH + 255)/256, 256>>>(W1, W2, bat);

    // CSR build
    k_count<<<(GE+255)/256, 256>>>(ei);
    k_scan1<<<GG*TILES, 1024>>>();
    k_scan3m<<<GG*TILES, 1024>>>();
    k_fill<<<(GE+255)/256, 256>>>(ei);

    // layer 1 fused: gather fp8 x + matmul + relu -> fp8 a1
    k_fused<FIN><<<(GN+127)/128, 256, smem1>>>(p_xq, p_w1h, b1, p_a1q);
    // layer 2 fused: gather fp8 a1 + matmul + relu -> fp8 a2
    k_fused<HH><<<(GN+127)/128, 256, smem2>>>(p_a1q, p_w2h, b2, p_a2q);

    // mean pooling per (graph, bucket)
    k_pool2<<<GG*BB, 256>>>();

    // fused attention + projections + mean over B
    k_attall<<<BB, 384>>>(ipw, ipb, opw, opb);

    // final linear + affine
    k_final<<<(NNODES+7)/8, 256>>>(lw, lb, out);
}

// round 16
// speedup vs baseline: 1.2195x; 1.0161x over previous
#include <cuda_runtime.h>
#include <cuda_fp16.h>
#include <stdint.h>
#include <math.h>

#define GG 4
#define NN 50000
#define EE 800000
#define BB 32
#define FIN 64
#define HH 128
#define NHEADS 8
#define HD 16
#define GN (GG*NN)
#define GE (GG*EE)
#define GBH (GG*BB*HH)
#define NNODES 50000
#define TILES 49   // ceil(NN/1024)

// ---------------- scratch (device globals; no allocation allowed) -------------
__device__ unsigned char g_xq[(size_t)GN*FIN];  // di*x as e4m3 fp8 (prescaled)
__device__ unsigned char g_a1q[(size_t)GN*HH];  // di*relu(layer1) as e4m3 fp8 (prescaled)
__device__ unsigned char g_a2q[(size_t)GN*HH];  // relu(layer2) as e4m3 fp8
__device__ __half g_w1h[FIN*HH];
__device__ __half g_w2h[HH*HH];
__device__ int   g_degi[GN];
__device__ float g_dinv[GN];
__device__ int   g_off[GG*(NN+1)];
__device__ int   g_cur[GN];
__device__ int   g_tsum[GG*TILES];
__device__ unsigned g_csr[(size_t)GE];      // row index (4B, aligned)
__device__ int   g_bstart[GG*(BB+1)];
__device__ float g_emb[GBH];                // pooled means
__device__ float g_pooled[GG*HH];

// ---------------- mma / ldmatrix / fp8 helpers -------------------------------------
__device__ __forceinline__ unsigned cvta_sm(const void* p) {
    return (unsigned)__cvta_generic_to_shared(p);
}
__device__ __forceinline__ void ldmx4(unsigned& r0, unsigned& r1, unsigned& r2, unsigned& r3, unsigned a) {
    asm volatile("ldmatrix.sync.aligned.m8n8.x4.shared.b16 {%0,%1,%2,%3},[%4];"
        : "=r"(r0), "=r"(r1), "=r"(r2), "=r"(r3) : "r"(a));
}
__device__ __forceinline__ void ldmx4t(unsigned& r0, unsigned& r1, unsigned& r2, unsigned& r3, unsigned a) {
    asm volatile("ldmatrix.sync.aligned.m8n8.x4.trans.shared.b16 {%0,%1,%2,%3},[%4];"
        : "=r"(r0), "=r"(r1), "=r"(r2), "=r"(r3) : "r"(a));
}
__device__ __forceinline__ void mma16816(float* d, unsigned a0, unsigned a1, unsigned a2, unsigned a3,
                                         unsigned b0, unsigned b1) {
    asm volatile("mma.sync.aligned.m16n8k16.row.col.f32.f16.f16.f32 "
        "{%0,%1,%2,%3},{%4,%5,%6,%7},{%8,%9},{%0,%1,%2,%3};"
        : "+f"(d[0]), "+f"(d[1]), "+f"(d[2]), "+f"(d[3])
        : "r"(a0), "r"(a1), "r"(a2), "r"(a3), "r"(b0), "r"(b1));
}
__device__ __forceinline__ float2 fp8x2_f2(unsigned short us) {
    unsigned h2;
    asm("cvt.rn.f16x2.e4m3x2 %0, %1;" : "=r"(h2) : "h"(us));
    return __half22float2(*(__half2*)&h2);
}
__device__ __forceinline__ unsigned short f2_fp8x2(float lo, float hi) {
    unsigned short us;
    asm("cvt.rn.satfinite.e4m3x2.f32 %0, %1, %2;" : "=h"(us) : "f"(hi), "f"(lo));
    return us;
}

// ---------------- conversions ------------------------------------------------------
// x (fp32) -> e4m3 fp8 prescaled by dinv[node]; MUST run after k_scan1
__global__ void k_xcvt(const float* __restrict__ x) {
    size_t i = (size_t)blockIdx.x*blockDim.x + threadIdx.x;
    if (i >= (size_t)GN*FIN/8) return;
    int node = (int)(i >> 3);
    float di = g_dinv[node];
    const float4* xs = (const float4*)x;
    float4 f0 = xs[2*i], f1 = xs[2*i+1];
    unsigned short q0 = f2_fp8x2(f0.x*di, f0.y*di);
    unsigned short q1 = f2_fp8x2(f0.z*di, f0.w*di);
    unsigned short q2 = f2_fp8x2(f1.x*di, f1.y*di);
    unsigned short q3 = f2_fp8x2(f1.z*di, f1.w*di);
    uint2 o = make_uint2((unsigned)q0 | ((unsigned)q1 << 16),
                         (unsigned)q2 | ((unsigned)q3 << 16));
    ((uint2*)g_xq)[i] = o;
}
// merged: W conversions + pooled zero + bucket bounds
__global__ void k_misc(const float* __restrict__ W1, const float* __restrict__ W2,
                       const int* __restrict__ batch) {
    int i = blockIdx.x*blockDim.x + threadIdx.x;
    if (i < FIN*HH) g_w1h[i] = __float2half_rn(W1[i]);
    if (i < HH*HH)  g_w2h[i] = __float2half_rn(W2[i]);
    if (i < GG*HH)  g_pooled[i] = 0.f;
    if (i < GG*BB) {
        int g = i >> 5, b = i & 31;
        const int* bt = batch + (size_t)g*NN;
        int lo = 0, hi = NN;
        while (lo < hi) {
            int mid = (lo + hi) >> 1;
            if (bt[mid] < b) lo = mid + 1; else hi = mid;
        }
        g_bstart[g*(BB+1) + b] = lo;
        if (b == 0) g_bstart[g*(BB+1) + BB] = NN;
    }
}

// ---------------- CSR build ------------------------------------------------------
__global__ void k_count(const int* __restrict__ ei) {
    int idx = blockIdx.x*blockDim.x + threadIdx.x;
    if (idx >= GE) return;
    int g = idx / EE, e = idx - g*EE;
    int col = ei[(size_t)g*2*EE + EE + e];
    atomicAdd(&g_degi[g*NN + col], 1);
}
__global__ void k_scan1() {
    int g = blockIdx.x / TILES, t = blockIdx.x % TILES;
    int tid = threadIdx.x, lane = tid & 31, wid = tid >> 5;
    __shared__ int wtot[32];
    int i = t*1024 + tid;
    int c = (i < NN) ? g_degi[g*NN + i] : 0;
    int v = c;
#pragma unroll
    for (int o = 1; o < 32; o <<= 1) {
        int u = __shfl_up_sync(~0u, v, o);
        if (lane >= o) v += u;
    }
    if (lane == 31) wtot[wid] = v;
    __syncthreads();
    if (wid == 0) {
        int w2 = wtot[lane];
#pragma unroll
        for (int o = 1; o < 32; o <<= 1) {
            int u = __shfl_up_sync(~0u, w2, o);
            if (lane >= o) w2 += u;
        }
        wtot[lane] = w2;
    }
    __syncthreads();
    int excl = (wid > 0 ? wtot[wid-1] : 0) + v - c;
    if (i < NN) {
        g_off[g*(NN+1) + i] = excl;
        g_dinv[g*NN + i] = rsqrtf((float)(c + 1));
    }
    if (tid == 0) g_tsum[blockIdx.x] = wtot[31];
}
// scan2+scan3 merged: each block recomputes its tile base from g_tsum
__global__ void k_scan3m() {
    int g = blockIdx.x / TILES, t = blockIdx.x % TILES;
    int tid = threadIdx.x;
    __shared__ int part[64];
    __shared__ int sbase;
    if (tid < 64) part[tid] = (tid < t) ? g_tsum[g*TILES + tid] : 0;
    __syncthreads();
    if (tid < 32) {
        int v = part[tid] + part[tid + 32];
#pragma unroll
        for (int o = 16; o; o >>= 1) v += __shfl_xor_sync(~0u, v, o);
        if (tid == 0) sbase = v;
    }
    __syncthreads();
    int i = t*1024 + tid;
    if (i < NN) {
        int o = g_off[g*(NN+1) + i] + sbase;
        g_off[g*(NN+1) + i] = o;
        g_cur[g*NN + i] = o;
    }
    if (blockIdx.x == 0 && tid < GG)
        g_off[tid*(NN+1) + NN] = EE;
}
// pure permute: no dinv gathers, 4B records
__global__ void k_fill(const int* __restrict__ ei) {
    int idx = blockIdx.x*blockDim.x + threadIdx.x;
    if (idx >= GE) return;
    int g = idx / EE, e = idx - g*EE;
    const int* bp = ei + (size_t)g*2*EE;
    int row = bp[e], col = bp[EE + e];
    int pos = atomicAdd(&g_cur[g*NN + col], 1);
    g_csr[(size_t)g*EE + pos] = (unsigned)row;
}

// ---------------- fused gather + tensor-core matmul per layer ----------------------
// As_row = di * ( Σ_nb src'[row] + src'[col] ), src' prescaled by own dinv.
// out = relu( As @ W + b ) [* dinv if PRE] -> fp8 qout
// 256 threads; block = 128 nodes; champion gather structure; 4 N-quarter mma.
template<int K, bool PRE>
__global__ void __launch_bounds__(256, 5) k_fused(const unsigned char* __restrict__ src,
        const __half* __restrict__ Wh, const float* __restrict__ bias,
        unsigned char* __restrict__ qout) {
    constexpr int AS = K + 8;      // padded A row (halfs)
    constexpr int WS = 40;         // quarter-N W tile row stride (32+8 halfs)
    extern __shared__ __half smh[];
    __half* As = smh;              // 128 * AS
    __half* Ws = smh + 128*AS;     // K * WS (one N-quarter at a time)
    int tid = threadIdx.x, wid = tid >> 5, lane = tid & 31;
    int base = blockIdx.x * 128;

    // gather phase: warp handles 16 local rows
    for (int t = 0; t < 16; t++) {
        int rl = wid*16 + t;
        int w = base + rl;
        if (w < GN) {
            int g = w / NN, n = w - g*NN;
            const unsigned char* xq = src + (size_t)g*NN*K;
            float di = g_dinv[w];
            int s = g_off[g*(NN+1) + n], e2 = g_off[g*(NN+1) + n + 1];
            const unsigned* cs = g_csr + (size_t)g*EE;
            if (K == FIN) {
                float a0, a1;
                {
                    float2 f = fp8x2_f2(*(const unsigned short*)(xq + (size_t)n*K + lane*2));
                    a0 = f.x; a1 = f.y;
                }
                int i = s;
                for (; i + 1 < e2; i += 2) {
                    unsigned r0 = __ldg(&cs[i]), r1 = __ldg(&cs[i+1]);
                    unsigned short va = *(const unsigned short*)(xq + (size_t)r0*K + lane*2);
                    unsigned short vb = *(const unsigned short*)(xq + (size_t)r1*K + lane*2);
                    float2 fa = fp8x2_f2(va), fb = fp8x2_f2(vb);
                    a0 += fa.x + fb.x;
                    a1 += fa.y + fb.y;
                }
                if (i < e2) {
                    unsigned r0 = __ldg(&cs[i]);
                    float2 fa = fp8x2_f2(*(const unsigned short*)(xq + (size_t)r0*K + lane*2));
                    a0 += fa.x;
                    a1 += fa.y;
                }
                *(__half2*)(As + rl*AS + lane*2) = __floats2half2_rn(a0*di, a1*di);
            } else {
                float a0, a1, a2, a3;
                {
                    unsigned v = *(const unsigned*)(xq + (size_t)n*K + lane*4);
                    float2 f0 = fp8x2_f2((unsigned short)(v & 0xFFFFu));
                    float2 f1 = fp8x2_f2((unsigned short)(v >> 16));
                    a0 = f0.x; a1 = f0.y; a2 = f1.x; a3 = f1.y;
                }
                int i = s;
                for (; i + 1 < e2; i += 2) {
                    unsigned r0 = __ldg(&cs[i]), r1 = __ldg(&cs[i+1]);
                    unsigned va = *(const unsigned*)(xq + (size_t)r0*K + lane*4);
                    unsigned vb = *(const unsigned*)(xq + (size_t)r1*K + lane*4);
                    float2 fa0 = fp8x2_f2((unsigned short)(va & 0xFFFFu));
                    float2 fa1 = fp8x2_f2((unsigned short)(va >> 16));
                    float2 fb0 = fp8x2_f2((unsigned short)(vb & 0xFFFFu));
                    float2 fb1 = fp8x2_f2((unsigned short)(vb >> 16));
                    a0 += fa0.x + fb0.x;
                    a1 += fa0.y + fb0.y;
                    a2 += fa1.x + fb1.x;
                    a3 += fa1.y + fb1.y;
                }
                if (i < e2) {
                    unsigned r0 = __ldg(&cs[i]);
                    unsigned va = *(const unsigned*)(xq + (size_t)r0*K + lane*4);
                    float2 fa0 = fp8x2_f2((unsigned short)(va & 0xFFFFu));
                    float2 fa1 = fp8x2_f2((unsigned short)(va >> 16));
                    a0 += fa0.x;
                    a1 += fa0.y;
                    a2 += fa1.x;
                    a3 += fa1.y;
                }
                uint2 o;
                *(__half2*)&o.x = __floats2half2_rn(a0*di, a1*di);
                *(__half2*)&o.y = __floats2half2_rn(a2*di, a3*di);
                *(uint2*)(As + rl*AS + lane*4) = o;
            }
        } else {
            if (K == FIN) *(__half2*)(As + rl*AS + lane*2) = __floats2half2_rn(0.f, 0.f);
            else *(uint2*)(As + rl*AS + lane*4) = make_uint2(0u, 0u);
        }
    }
    __syncthreads();

    // mma phase: four N-quarters, d[4][4] accumulators each
    unsigned a_sm = cvta_sm(As);
    unsigned w_sm = cvta_sm(Ws);
    int arow = wid*16 + (lane & 15);
    int asel = (lane >> 4) * 8;
    int krow = lane & 15;
    int gq = lane >> 2, tq = lane & 3;
    int row0 = base + wid*16 + gq;
    int row1 = row0 + 8;
    float sc0 = 1.f, sc1 = 1.f;
    if (PRE) {
        if (row0 < GN) sc0 = g_dinv[row0];
        if (row1 < GN) sc1 = g_dinv[row1];
    }

#pragma unroll
    for (int nh = 0; nh < 4; nh++) {
        for (int idx = tid; idx < K*4; idx += 256) {
            int r = idx >> 2, c8 = (idx & 3) << 3;
            *(uint4*)(Ws + r*WS + c8) = *(const uint4*)(Wh + r*HH + nh*32 + c8);
        }
        __syncthreads();

        float d[4][4];
#pragma unroll
        for (int t = 0; t < 4; t++) {
            d[t][0] = 0.f; d[t][1] = 0.f; d[t][2] = 0.f; d[t][3] = 0.f;
        }
        for (int kk = 0; kk < K/16; kk++) {
            unsigned a0, a1, a2, a3;
            ldmx4(a0, a1, a2, a3, a_sm + (unsigned)(arow*AS + kk*16 + asel)*2u);
#pragma unroll
            for (int nt = 0; nt < 2; nt++) {
                unsigned b0, b1, b2, b3;
                ldmx4t(b0, b1, b2, b3, w_sm + (unsigned)((kk*16 + krow)*WS + nt*16 + asel)*2u);
                mma16816(d[2*nt],   a0, a1, a2, a3, b0, b1);
                mma16816(d[2*nt+1], a0, a1, a2, a3, b2, b3);
            }
        }

        // epilogue for this quarter: bias + relu (+ dinv prescale if PRE) -> fp8
#pragma unroll
        for (int nt = 0; nt < 4; nt++) {
            int c0 = nh*32 + nt*8 + tq*2;
            float2 bc = *(const float2*)(bias + c0);
            float v00 = fmaxf(d[nt][0] + bc.x, 0.f)*sc0;
            float v01 = fmaxf(d[nt][1] + bc.y, 0.f)*sc0;
            float v10 = fmaxf(d[nt][2] + bc.x, 0.f)*sc1;
            float v11 = fmaxf(d[nt][3] + bc.y, 0.f)*sc1;
            unsigned short q0 = f2_fp8x2(v00, v01);
            unsigned short q1 = f2_fp8x2(v10, v11);
            if (row0 < GN) *(unsigned short*)(qout + (size_t)row0*HH + c0) = q0;
            if (row1 < GN) *(unsigned short*)(qout + (size_t)row1*HH + c0) = q1;
        }
        __syncthreads();   // Ws reload safety for next quarter
    }
}

// ---------------- pooling (reads fp8 a2) --------------------------------------------
__global__ void __launch_bounds__(256) k_pool2() {
    int g = blockIdx.x / BB, b = blockIdx.x % BB;
    int s = g_bstart[g*(BB+1) + b], e = g_bstart[g*(BB+1) + b + 1];
    int cnt = e - s;
    int tid = threadIdx.x;
    int cg = tid & 31, r0 = tid >> 5;
    float4 acc = make_float4(0.f, 0.f, 0.f, 0.f);
    const unsigned* a2 = (const unsigned*)(g_a2q + (size_t)g*NN*HH);
    for (int n = s + r0; n < e; n += 8) {
        unsigned v = a2[(size_t)n*32 + cg];
        float2 f0 = fp8x2_f2((unsigned short)(v & 0xFFFFu));
        float2 f1 = fp8x2_f2((unsigned short)(v >> 16));
        acc.x += f0.x; acc.y += f0.y; acc.z += f1.x; acc.w += f1.y;
    }
    __shared__ float4 sacc[256];
    sacc[tid] = acc;
    __syncthreads();
    if (tid < 32) {
        float4 t = sacc[tid];
#pragma unroll
        for (int r = 1; r < 8; r++) {
            float4 o = sacc[tid + 32*r];
            t.x += o.x; t.y += o.y; t.z += o.z; t.w += o.w;
        }
        float inv = (cnt > 0) ? 1.0f/(float)cnt : 0.0f;
        *(float4*)(g_emb + (size_t)blockIdx.x*HH + tid*4) =
            make_float4(t.x*inv, t.y*inv, t.z*inv, t.w*inv);
    }
}

// ---------------- fused attention (one block per batch-bucket b) -------------------
__global__ void __launch_bounds__(384) k_attall(const float* __restrict__ ipw,
        const float* __restrict__ ipb, const float* __restrict__ opw,
        const float* __restrict__ opb) {
    __shared__ float emb[GG][HH];
    __shared__ float qkv[3][GG][HH];
    __shared__ float sc[NHEADS][GG][GG];
    __shared__ float att[GG][HH];
    int b = blockIdx.x, tid = threadIdx.x;
    for (int i = tid; i < GG*HH; i += 384) {
        int g = i >> 7, c = i & 127;
        emb[g][c] = g_emb[(g*BB + b)*HH + c];
    }
    __syncthreads();
#pragma unroll
    for (int t = 0; t < 4; t++) {
        int o = tid + t*384;
        int sec = o / 512, rem = o - sec*512, g = rem >> 7, i = rem & 127;
        const float* wrow = ipw + (size_t)(sec*HH + i)*HH;
        float s = ipb[sec*HH + i];
#pragma unroll 8
        for (int j = 0; j < HH; j++) s += emb[g][j]*wrow[j];
        qkv[sec][g][i] = s;
    }
    __syncthreads();
    if (tid < 128) {
        int h = tid >> 4, g = (tid >> 2) & 3, k = tid & 3;
        float s = 0.f;
#pragma unroll
        for (int dd = 0; dd < HD; dd++) s += qkv[0][g][h*HD + dd]*qkv[1][k][h*HD + dd];
        sc[h][g][k] = s*0.25f;
    }
    __syncthreads();
    for (int o = tid; o < GG*HH; o += 384) {
        int g = o >> 7, i = o & 127, h = i >> 4;
        float s0 = sc[h][g][0], s1 = sc[h][g][1], s2 = sc[h][g][2], s3 = sc[h][g][3];
        float m = fmaxf(fmaxf(s0, s1), fmaxf(s2, s3));
        float e0 = expf(s0 - m), e1 = expf(s1 - m), e2 = expf(s2 - m), e3 = expf(s3 - m);
        float inv = 1.f/(e0 + e1 + e2 + e3);
        att[g][i] = (e0*qkv[2][0][i] + e1*qkv[2][1][i] + e2*qkv[2][2][i] + e3*qkv[2][3][i])*inv;
    }
    __syncthreads();
    for (int o = tid; o < GG*HH; o += 384) {
        int g = o >> 7, i = o & 127;
        const float* wrow = opw + (size_t)i*HH;
        float s = opb[i];
#pragma unroll 8
        for (int j = 0; j < HH; j++) s += att[g][j]*wrow[j];
        atomicAdd(&g_pooled[g*HH + i], s*(1.0f/BB));
    }
}

// ---------------- final linear ------------------------------------------------------
__global__ void k_final(const float* __restrict__ lw, const float* __restrict__ lb,
                        float* __restrict__ out) {
    __shared__ float ps[GG*HH];
    int tid = threadIdx.x;
    for (int i = tid; i < GG*HH; i += 256) ps[i] = g_pooled[i];
    __syncthreads();
    int n = blockIdx.x*8 + (tid >> 5);
    if (n >= NNODES) return;
    int lane = tid & 31;
    float4 lv = *(const float4*)(lw + (size_t)n*HH + lane*4);
    float d[GG];
#pragma unroll
    for (int g = 0; g < GG; g++) {
        const float* pg = ps + g*HH + lane*4;
        d[g] = lv.x*pg[0] + lv.y*pg[1] + lv.z*pg[2] + lv.w*pg[3];
    }
#pragma unroll
    for (int g = 0; g < GG; g++)
        for (int off = 16; off; off >>= 1)
            d[g] += __shfl_xor_sync(~0u, d[g], off);
    if (lane == 0) {
        float bn = lb[n];
#pragma unroll
        for (int g = 0; g < GG; g++)
            out[(size_t)g*NNODES + n] = (d[g] + bn)*60.0f + 50.0f;
    }
}

// ---------------- launch -------------------------------------------------------------
extern "C" void kernel_launch(void* const* d_in, const int* in_sizes, int n_in,
                              void* d_out, int out_size) {
    const float* x   = (const float*)d_in[0];
    const int*   ei  = (const int*)  d_in[1];
    const int*   bat = (const int*)  d_in[2];
    const float* W1  = (const float*)d_in[3];
    const float* b1  = (const float*)d_in[4];
    const float* W2  = (const float*)d_in[5];
    const float* b2  = (const float*)d_in[6];
    const float* ipw = (const float*)d_in[7];
    const float* ipb = (const float*)d_in[8];
    const float* opw = (const float*)d_in[9];
    const float* opb = (const float*)d_in[10];
    const float* lw  = (const float*)d_in[11];
    const float* lb  = (const float*)d_in[12];
    float* out = (float*)d_out;

    __half *p_w1h, *p_w2h;
    unsigned char *p_xq, *p_a1q, *p_a2q;
    int *p_degi;
    cudaGetSymbolAddress((void**)&p_xq,   g_xq);
    cudaGetSymbolAddress((void**)&p_a1q,  g_a1q);
    cudaGetSymbolAddress((void**)&p_a2q,  g_a2q);
    cudaGetSymbolAddress((void**)&p_w1h,  g_w1h);
    cudaGetSymbolAddress((void**)&p_w2h,  g_w2h);
    cudaGetSymbolAddress((void**)&p_degi, g_degi);

    const int smem1 = (128*(FIN+8) + FIN*40)*2;   // 23552 B
    const int smem2 = (128*(HH+8) + HH*40)*2;     // 45056 B
    cudaFuncSetAttribute((k_fused<FIN, true>),  cudaFuncAttributeMaxDynamicSharedMemorySize, smem1);
    cudaFuncSetAttribute((k_fused<HH, false>),  cudaFuncAttributeMaxDynamicSharedMemorySize, smem2);

    // misc first (no dinv dependency)
    cudaMemsetAsync(p_degi, 0, GN*sizeof(int), 0);
    k_misc<<<(HH*HH + 255)/256, 256>>>(W1, W2, bat);

    // CSR build; dinv ready after scan1; xcvt needs dinv
    k_count<<<(GE+255)/256, 256>>>(ei);
    k_scan1<<<GG*TILES, 1024>>>();
    k_xcvt<<<(GN*FIN/8 + 255)/256, 256>>>(x);
    k_scan3m<<<GG*TILES, 1024>>>();
    k_fill<<<(GE+255)/256, 256>>>(ei);

    // layer 1 fused: gather prescaled fp8 x + matmul + relu -> prescaled fp8 a1
    k_fused<FIN, true><<<(GN+127)/128, 256, smem1>>>(p_xq, p_w1h, b1, p_a1q);
    // layer 2 fused: gather prescaled fp8 a1 + matmul + relu -> fp8 a2
    k_fused<HH, false><<<(GN+127)/128, 256, smem2>>>(p_a1q, p_w2h, b2, p_a2q);

    // mean pooling per (graph, bucket)
    k_pool2<<<GG*BB, 256>>>();

    // fused attention + projections + mean over B
    k_attall<<<BB, 384>>>(ipw, ipb, opw, opb);

    // final linear + affine
    k_final<<<(NNODES+7)/8, 256>>>(lw, lb, out);
}